// round 3
// baseline (speedup 1.0000x reference)
#include <cuda_runtime.h>
#include <math.h>

#define HW 16384
#define LOG100f 4.605170185988092f

__device__ float g_x1[16u * HW * 128u];   // 134 MB scratch: x1 token-major [tok][128]
__device__ float g_bias16[4 * 64 * 64];   // 16*sigmoid(cpb bias) [h][t][u]

// ------------------------------ K0: bias table ------------------------------
__global__ void k0_bias(const float* __restrict__ w1, const float* __restrict__ b1,
                        const float* __restrict__ w2) {
    __shared__ float tab[225][4];
    int tid = threadIdx.x;
    if (tid < 225) {
        int a = tid / 15, bb = tid % 15;
        float v0 = (a - 7) * (8.0f / 7.0f), v1 = (bb - 7) * (8.0f / 7.0f);
        float g0 = copysignf(log2f(fabsf(v0) + 1.0f) * (1.0f / 3.0f), v0);
        float g1 = copysignf(log2f(fabsf(v1) + 1.0f) * (1.0f / 3.0f), v1);
        float o0 = 0, o1 = 0, o2 = 0, o3 = 0;
        for (int j = 0; j < 512; j++) {
            float hv = fmaxf(w1[2 * j] * g0 + w1[2 * j + 1] * g1 + b1[j], 0.0f);
            o0 += hv * w2[j];        o1 += hv * w2[512 + j];
            o2 += hv * w2[1024 + j]; o3 += hv * w2[1536 + j];
        }
        tab[tid][0] = o0; tab[tid][1] = o1; tab[tid][2] = o2; tab[tid][3] = o3;
    }
    __syncthreads();
    for (int e = tid; e < 4 * 64 * 64; e += blockDim.x) {
        int h = e >> 12, i = (e >> 6) & 63, j = e & 63;
        int dy = (i >> 3) - (j >> 3) + 7, dx = (i & 7) - (j & 7) + 7;
        float v = tab[dy * 15 + dx][h];
        g_bias16[e] = 16.0f / (1.0f + expf(-v));
    }
}

// ------------------------------ K1: attention -------------------------------
// smem offsets (floats)
#define OF_XT   0                  // [128][64] window channel-major (== shortcut)
#define OF_W    8192               // weight stage [128][64]; reused as ATTN/VT
#define OF_ATTN 8192               // [64][68]
#define OF_VT   8192               // [64][36]
#define OF_PT   12544              // [64][68]
#define OF_QKV  16896              // [384][68]; reused: Pout [64][132]
#define OF_O    43008              // [128][68]
#define OF_IQ   51712
#define OF_IK   51776
#define OF_RG   51840
#define K1_SMEM (51904 * 4)        // 207616 bytes

__global__ void __launch_bounds__(256, 1)
k1_attn(const float* __restrict__ x,
        const float* __restrict__ n1w, const float* __restrict__ n1b,
        const float* __restrict__ qkvw,
        const float* __restrict__ qb, const float* __restrict__ vb,
        const float* __restrict__ ls,
        const float* __restrict__ pw, const float* __restrict__ pb) {
    extern __shared__ float sm[];
    int tid = threadIdx.x;
    int b = blockIdx.x >> 8, widx = blockIdx.x & 255;
    int wy = widx >> 4, wx = widx & 15;

    // phase 0: gather shifted window, channel-major
    {
        const float* xb = x + (size_t)b * 128 * HW;
        int wbase = wx * 8 + 4;
#pragma unroll
        for (int it = 0; it < 4; it++) {
            int p = tid + it * 256;
            int c = p >> 3, ti = p & 7;
            int h = (wy * 8 + ti + 4) & 127;
            const float* row = xb + c * HW + h * 128;
            float* dst = &sm[OF_XT + c * 64 + ti * 8];
#pragma unroll
            for (int tj = 0; tj < 8; tj++) dst[tj] = row[(wbase + tj) & 127];
        }
        if (tid < 64) {
            int ti = tid >> 3, tj = tid & 7;
            int hs = wy * 8 + ti, ws = wx * 8 + tj;
            int hr = hs < 120 ? 0 : (hs < 124 ? 1 : 2);
            int wr = ws < 120 ? 0 : (ws < 124 ? 1 : 2);
            sm[OF_RG + tid] = (float)(hr * 3 + wr);
        }
    }

    int tg = tid >> 4, cg = tid & 15;
    int t0 = tg * 4, c0 = cg * 4;

    // phase 1: QKV GEMM (6 chunks of 64 cols)
    for (int ch = 0; ch < 6; ch++) {
        __syncthreads();
#pragma unroll
        for (int it = 0; it < 8; it++) {
            int p = tid + it * 256;
            int cl = p & 63, kq = p >> 6;
            float4 wv = *(const float4*)&qkvw[(ch * 64 + cl) * 128 + kq * 4];
            sm[OF_W + (kq * 4 + 0) * 64 + cl] = wv.x;
            sm[OF_W + (kq * 4 + 1) * 64 + cl] = wv.y;
            sm[OF_W + (kq * 4 + 2) * 64 + cl] = wv.z;
            sm[OF_W + (kq * 4 + 3) * 64 + cl] = wv.w;
        }
        __syncthreads();
        float acc[4][4];
#pragma unroll
        for (int j = 0; j < 4; j++) {
            int col = ch * 64 + c0 + j;
            float bias = col < 128 ? qb[col] : (col >= 256 ? vb[col - 256] : 0.0f);
#pragma unroll
            for (int i = 0; i < 4; i++) acc[i][j] = bias;
        }
#pragma unroll 4
        for (int k = 0; k < 128; k++) {
            float4 av = *(const float4*)&sm[OF_XT + k * 64 + t0];
            float4 wv = *(const float4*)&sm[OF_W + k * 64 + c0];
            float a4[4] = {av.x, av.y, av.z, av.w};
            float w4[4] = {wv.x, wv.y, wv.z, wv.w};
#pragma unroll
            for (int i = 0; i < 4; i++)
#pragma unroll
                for (int j = 0; j < 4; j++) acc[i][j] += a4[i] * w4[j];
        }
#pragma unroll
        for (int j = 0; j < 4; j++)
#pragma unroll
            for (int i = 0; i < 4; i++)
                sm[OF_QKV + (ch * 64 + c0 + j) * 68 + t0 + i] = acc[i][j];
    }

    // phase 2: attention per head
    for (int h = 0; h < 4; h++) {
        __syncthreads();
        if (tid < 128) {
            int t = tid & 63;
            int base = (tid < 64 ? 0 : 128) + h * 32;
            float s = 0.f;
#pragma unroll
            for (int d = 0; d < 32; d++) {
                float v = sm[OF_QKV + (base + d) * 68 + t];
                s += v * v;
            }
            sm[(tid < 64 ? OF_IQ : OF_IK) + t] = 1.0f / fmaxf(sqrtf(s), 1e-12f);
        }
        __syncthreads();
        {
            float scale = __expf(fminf(ls[h], LOG100f));
            int u0 = c0;
            float acc[4][4] = {};
#pragma unroll 4
            for (int d = 0; d < 32; d++) {
                float4 qv = *(const float4*)&sm[OF_QKV + (h * 32 + d) * 68 + t0];
                float4 kv = *(const float4*)&sm[OF_QKV + (128 + h * 32 + d) * 68 + u0];
                float q4[4] = {qv.x, qv.y, qv.z, qv.w};
                float k4[4] = {kv.x, kv.y, kv.z, kv.w};
#pragma unroll
                for (int i = 0; i < 4; i++)
#pragma unroll
                    for (int j = 0; j < 4; j++) acc[i][j] += q4[i] * k4[j];
            }
            float iq[4], ik[4], rt[4], ru[4];
#pragma unroll
            for (int i = 0; i < 4; i++) {
                iq[i] = sm[OF_IQ + t0 + i];
                ik[i] = sm[OF_IK + u0 + i];
                rt[i] = sm[OF_RG + t0 + i];
                ru[i] = sm[OF_RG + u0 + i];
            }
#pragma unroll
            for (int i = 0; i < 4; i++)
#pragma unroll
                for (int j = 0; j < 4; j++) {
                    float msk = (rt[i] != ru[j]) ? -100.0f : 0.0f;
                    float bia = g_bias16[(h * 64 + t0 + i) * 64 + u0 + j];
                    sm[OF_ATTN + (t0 + i) * 68 + u0 + j] =
                        acc[i][j] * iq[i] * ik[j] * scale + bia + msk;
                }
        }
        __syncthreads();
        if (tid < 64) {   // softmax row tid, write P transposed
            float* row = &sm[OF_ATTN + tid * 68];
            float mx = -1e30f;
            for (int u = 0; u < 64; u++) mx = fmaxf(mx, row[u]);
            float s = 0.f;
            for (int u = 0; u < 64; u++) { float e = __expf(row[u] - mx); row[u] = e; s += e; }
            float inv = 1.0f / s;
            for (int u = 0; u < 64; u++) sm[OF_PT + u * 68 + tid] = row[u] * inv;
        }
        __syncthreads();
#pragma unroll
        for (int it = 0; it < 8; it++) {   // stage V transposed [u][d]
            int p = tid + it * 256;
            int u = p & 63, d = p >> 6;
            sm[OF_VT + u * 36 + d] = sm[OF_QKV + (256 + h * 32 + d) * 68 + u];
        }
        __syncthreads();
        if (tid < 128) {   // PV -> O channel-major
            int tg2 = tid >> 3, dg = tid & 7;
            int tt0 = tg2 * 4, d0 = dg * 4;
            float acc[4][4] = {};
#pragma unroll 2
            for (int u = 0; u < 64; u++) {
                float4 pv = *(const float4*)&sm[OF_PT + u * 68 + tt0];
                float4 vv = *(const float4*)&sm[OF_VT + u * 36 + d0];
                float p4[4] = {pv.x, pv.y, pv.z, pv.w};
                float v4[4] = {vv.x, vv.y, vv.z, vv.w};
#pragma unroll
                for (int i = 0; i < 4; i++)
#pragma unroll
                    for (int j = 0; j < 4; j++) acc[i][j] += p4[i] * v4[j];
            }
#pragma unroll
            for (int j = 0; j < 4; j++)
#pragma unroll
                for (int i = 0; i < 4; i++)
                    sm[OF_O + (h * 32 + d0 + j) * 68 + tt0 + i] = acc[i][j];
        }
    }

    // phase 3: proj GEMM -> Pout row-major in QKV region
    for (int ch = 0; ch < 2; ch++) {
        __syncthreads();
#pragma unroll
        for (int it = 0; it < 8; it++) {
            int p = tid + it * 256;
            int cl = p & 63, kq = p >> 6;
            float4 wv = *(const float4*)&pw[(ch * 64 + cl) * 128 + kq * 4];
            sm[OF_W + (kq * 4 + 0) * 64 + cl] = wv.x;
            sm[OF_W + (kq * 4 + 1) * 64 + cl] = wv.y;
            sm[OF_W + (kq * 4 + 2) * 64 + cl] = wv.z;
            sm[OF_W + (kq * 4 + 3) * 64 + cl] = wv.w;
        }
        __syncthreads();
        float acc[4][4];
#pragma unroll
        for (int j = 0; j < 4; j++) {
            float bias = pb[ch * 64 + c0 + j];
#pragma unroll
            for (int i = 0; i < 4; i++) acc[i][j] = bias;
        }
#pragma unroll 4
        for (int k = 0; k < 128; k++) {
            float4 av = *(const float4*)&sm[OF_O + k * 68 + t0];
            float4 wv = *(const float4*)&sm[OF_W + k * 64 + c0];
            float a4[4] = {av.x, av.y, av.z, av.w};
            float w4[4] = {wv.x, wv.y, wv.z, wv.w};
#pragma unroll
            for (int i = 0; i < 4; i++)
#pragma unroll
                for (int j = 0; j < 4; j++) acc[i][j] += a4[i] * w4[j];
        }
#pragma unroll
        for (int i = 0; i < 4; i++)
#pragma unroll
            for (int j = 0; j < 4; j++)
                sm[OF_QKV + (t0 + i) * 132 + ch * 64 + c0 + j] = acc[i][j];
    }

    // phase 4: LN + residual -> g_x1 at un-shifted position
    __syncthreads();
    {
        int t = tid >> 2, lane = tid & 3;
        const float* prow = &sm[OF_QKV + t * 132];
        int cb = lane * 32;
        float s1 = 0.f, s2 = 0.f;
#pragma unroll 8
        for (int c = 0; c < 32; c++) {
            float v = prow[cb + c];
            s1 += v; s2 += v * v;
        }
        s1 += __shfl_xor_sync(0xffffffffu, s1, 1);
        s2 += __shfl_xor_sync(0xffffffffu, s2, 1);
        s1 += __shfl_xor_sync(0xffffffffu, s1, 2);
        s2 += __shfl_xor_sync(0xffffffffu, s2, 2);
        float mu = s1 * (1.0f / 128.0f);
        float var = fmaxf(s2 * (1.0f / 128.0f) - mu * mu, 0.0f);
        float rs = rsqrtf(var + 1e-5f);
        int ti = t >> 3, tj = t & 7;
        int hh = (wy * 8 + ti + 4) & 127;
        int ww = (wx * 8 + tj + 4) & 127;
        float* dst = &g_x1[((size_t)b * HW + hh * 128 + ww) * 128];
#pragma unroll 8
        for (int c = 0; c < 32; c++) {
            int cc = cb + c;
            float lnv = (prow[cc] - mu) * rs * n1w[cc] + n1b[cc];
            dst[cc] = sm[OF_XT + cc * 64 + t] + lnv;
        }
    }
}

// ------------------------------ K2: MLP -------------------------------------
#define O2_X  0         // [64][132] x1 token-major
#define O2_W1 8448      // [128][64] fc1 weight stage (k-major)
#define O2_W2 16640     // [64][64]  fc2 weight slice (k-major)
#define O2_H  20736     // [64][68]  hidden chunk, token-major
#define O2_Y  25088     // [64][133] mlp out / x2
#define K2_SMEM (33600 * 4)   // 134400 bytes

__global__ void __launch_bounds__(256, 1)
k2_mlp(const float* __restrict__ n2w, const float* __restrict__ n2b,
       const float* __restrict__ w1, const float* __restrict__ b1,
       const float* __restrict__ w2, const float* __restrict__ b2,
       float* __restrict__ out) {
    extern __shared__ float sm[];
    int tid = threadIdx.x;
    int p0 = blockIdx.x * 64;
    int b = p0 >> 14, h = (p0 >> 7) & 127, w0 = p0 & 127;

    // load x1 (coalesced), token-major stride 132
#pragma unroll
    for (int it = 0; it < 8; it++) {
        int idx = it * 256 + tid;
        int t = idx >> 5, cq = idx & 31;
        float4 v = *(const float4*)&g_x1[((size_t)p0 + t) * 128 + cq * 4];
        *(float4*)&sm[O2_X + t * 132 + cq * 4] = v;
    }
    int tg = tid >> 4, cg = tid & 15;
    int t0 = tg * 4, c0 = cg * 4;

    float acc2[2][4][4];
#pragma unroll
    for (int q = 0; q < 2; q++)
#pragma unroll
        for (int i = 0; i < 4; i++)
#pragma unroll
            for (int j = 0; j < 4; j++) acc2[q][i][j] = 0.f;

    for (int ch1 = 0; ch1 < 8; ch1++) {
        __syncthreads();
#pragma unroll
        for (int it = 0; it < 8; it++) {   // stage fc1 chunk [128k][64c]
            int p = tid + it * 256;
            int cl = p & 63, kq = p >> 6;
            float4 wv = *(const float4*)&w1[(ch1 * 64 + cl) * 128 + kq * 4];
            sm[O2_W1 + (kq * 4 + 0) * 64 + cl] = wv.x;
            sm[O2_W1 + (kq * 4 + 1) * 64 + cl] = wv.y;
            sm[O2_W1 + (kq * 4 + 2) * 64 + cl] = wv.z;
            sm[O2_W1 + (kq * 4 + 3) * 64 + cl] = wv.w;
        }
        __syncthreads();
        float acc[4][4];
#pragma unroll
        for (int j = 0; j < 4; j++) {
            float bias = b1[ch1 * 64 + c0 + j];
#pragma unroll
            for (int i = 0; i < 4; i++) acc[i][j] = bias;
        }
#pragma unroll 4
        for (int k = 0; k < 128; k++) {
            float a4[4];
#pragma unroll
            for (int i = 0; i < 4; i++) a4[i] = sm[O2_X + (t0 + i) * 132 + k];
            float4 wv = *(const float4*)&sm[O2_W1 + k * 64 + c0];
            float w4[4] = {wv.x, wv.y, wv.z, wv.w};
#pragma unroll
            for (int i = 0; i < 4; i++)
#pragma unroll
                for (int j = 0; j < 4; j++) acc[i][j] += a4[i] * w4[j];
        }
#pragma unroll
        for (int i = 0; i < 4; i++)
#pragma unroll
            for (int j = 0; j < 4; j++) {
                float v = acc[i][j];
                v = v / (1.0f + __expf(-v));   // silu
                sm[O2_H + (t0 + i) * 68 + c0 + j] = v;
            }
        for (int ch2 = 0; ch2 < 2; ch2++) {
            __syncthreads();
#pragma unroll
            for (int it = 0; it < 4; it++) {   // stage fc2 slice [64k][64c]
                int p = tid + it * 256;
                int cl = p & 63, kq = p >> 6;
                float4 wv = *(const float4*)&w2[(ch2 * 64 + cl) * 512 + ch1 * 64 + kq * 4];
                sm[O2_W2 + (kq * 4 + 0) * 64 + cl] = wv.x;
                sm[O2_W2 + (kq * 4 + 1) * 64 + cl] = wv.y;
                sm[O2_W2 + (kq * 4 + 2) * 64 + cl] = wv.z;
                sm[O2_W2 + (kq * 4 + 3) * 64 + cl] = wv.w;
            }
            __syncthreads();
#pragma unroll 4
            for (int k = 0; k < 64; k++) {
                float a4[4];
#pragma unroll
                for (int i = 0; i < 4; i++) a4[i] = sm[O2_H + (t0 + i) * 68 + k];
                float4 wv = *(const float4*)&sm[O2_W2 + k * 64 + c0];
                float w4[4] = {wv.x, wv.y, wv.z, wv.w};
#pragma unroll
                for (int i = 0; i < 4; i++)
#pragma unroll
                    for (int j = 0; j < 4; j++) acc2[ch2][i][j] += a4[i] * w4[j];
            }
        }
    }
    // write Y = mlp out
#pragma unroll
    for (int q = 0; q < 2; q++)
#pragma unroll
        for (int i = 0; i < 4; i++)
#pragma unroll
            for (int j = 0; j < 4; j++)
                sm[O2_Y + (t0 + i) * 133 + q * 64 + c0 + j] = acc2[q][i][j] + b2[q * 64 + c0 + j];
    __syncthreads();
    // LN + residual, in place into Y
    {
        int t = tid >> 2, lane = tid & 3;
        float* yrow = &sm[O2_Y + t * 133];
        int cb = lane * 32;
        float s1 = 0.f, s2 = 0.f;
#pragma unroll 8
        for (int c = 0; c < 32; c++) {
            float v = yrow[cb + c];
            s1 += v; s2 += v * v;
        }
        s1 += __shfl_xor_sync(0xffffffffu, s1, 1);
        s2 += __shfl_xor_sync(0xffffffffu, s2, 1);
        s1 += __shfl_xor_sync(0xffffffffu, s1, 2);
        s2 += __shfl_xor_sync(0xffffffffu, s2, 2);
        float mu = s1 * (1.0f / 128.0f);
        float var = fmaxf(s2 * (1.0f / 128.0f) - mu * mu, 0.0f);
        float rs = rsqrtf(var + 1e-5f);
#pragma unroll 8
        for (int c = 0; c < 32; c++) {
            int cc = cb + c;
            float lnv = (yrow[cc] - mu) * rs * n2w[cc] + n2b[cc];
            yrow[cc] = sm[O2_X + t * 132 + cc] + lnv;
        }
    }
    __syncthreads();
    // transposed store -> NCHW
    {
        float* ob = out + (size_t)b * 128 * HW + h * 128 + w0;
#pragma unroll
        for (int it = 0; it < 32; it++) {
            int idx = it * 256 + tid;
            int c = idx >> 6, ww = idx & 63;
            ob[(size_t)c * HW + ww] = sm[O2_Y + ww * 133 + c];
        }
    }
}

// ------------------------------ launch --------------------------------------
extern "C" void kernel_launch(void* const* d_in, const int* in_sizes, int n_in,
                              void* d_out, int out_size) {
    const float* x    = (const float*)d_in[0];
    const float* n1w  = (const float*)d_in[1];
    const float* n1b  = (const float*)d_in[2];
    const float* qkvw = (const float*)d_in[3];
    const float* qb   = (const float*)d_in[4];
    const float* vb   = (const float*)d_in[5];
    const float* ls   = (const float*)d_in[6];
    const float* cw1  = (const float*)d_in[7];
    const float* cb1  = (const float*)d_in[8];
    const float* cw2  = (const float*)d_in[9];
    const float* pw   = (const float*)d_in[10];
    const float* pb   = (const float*)d_in[11];
    const float* n2w  = (const float*)d_in[12];
    const float* n2b  = (const float*)d_in[13];
    const float* f1w  = (const float*)d_in[14];
    const float* f1b  = (const float*)d_in[15];
    const float* f2w  = (const float*)d_in[16];
    const float* f2b  = (const float*)d_in[17];
    float* out = (float*)d_out;

    cudaFuncSetAttribute(k1_attn, cudaFuncAttributeMaxDynamicSharedMemorySize, K1_SMEM);
    cudaFuncSetAttribute(k2_mlp,  cudaFuncAttributeMaxDynamicSharedMemorySize, K2_SMEM);

    k0_bias<<<1, 256>>>(cw1, cb1, cw2);
    k1_attn<<<4096, 256, K1_SMEM>>>(x, n1w, n1b, qkvw, qb, vb, ls, pw, pb);
    k2_mlp<<<4096, 256, K2_SMEM>>>(n2w, n2b, f1w, f1b, f2w, f2b, out);
}

// round 4
// speedup vs baseline: 2.1262x; 2.1262x over previous
#include <cuda_runtime.h>
#include <cuda_bf16.h>
#include <math.h>

#define HW 16384
#define LOG100f 4.605170185988092f

__device__ float g_x1[16u * HW * 128u];   // x1 token-major [tok][128]
__device__ float g_bias16[4 * 64 * 64];   // 16*sigmoid(cpb bias)
// pre-split weights, bf16 pairs packed in u32 along K
__device__ unsigned g_qkvh[24576], g_qkvl[24576];   // [384][64]
__device__ unsigned g_pwh[8192],   g_pwl[8192];     // [128][64]
__device__ unsigned g_f1h[32768],  g_f1l[32768];    // [512][64]
__device__ unsigned g_f2h[32768],  g_f2l[32768];    // [128][256]

// ---------------------------------------------------------------------------
__device__ __forceinline__ void mma_bf16(float d[4], unsigned a0, unsigned a1,
                                         unsigned a2, unsigned a3,
                                         unsigned b0, unsigned b1) {
    asm volatile(
        "mma.sync.aligned.m16n8k16.row.col.f32.bf16.bf16.f32 "
        "{%0,%1,%2,%3},{%4,%5,%6,%7},{%8,%9},{%0,%1,%2,%3};"
        : "+f"(d[0]), "+f"(d[1]), "+f"(d[2]), "+f"(d[3])
        : "r"(a0), "r"(a1), "r"(a2), "r"(a3), "r"(b0), "r"(b1));
}

__device__ __forceinline__ void split2(float v0, float v1, unsigned& hi, unsigned& lo) {
    __nv_bfloat16 h0 = __float2bfloat16(v0);
    __nv_bfloat16 h1 = __float2bfloat16(v1);
    float r0 = v0 - __bfloat162float(h0);
    float r1 = v1 - __bfloat162float(h1);
    __nv_bfloat16 l0 = __float2bfloat16(r0);
    __nv_bfloat16 l1 = __float2bfloat16(r1);
    hi = (unsigned)__bfloat16_as_ushort(h0) | ((unsigned)__bfloat16_as_ushort(h1) << 16);
    lo = (unsigned)__bfloat16_as_ushort(l0) | ((unsigned)__bfloat16_as_ushort(l1) << 16);
}

__device__ __forceinline__ float2 unpack2(unsigned u) {
    __nv_bfloat162 b = *reinterpret_cast<__nv_bfloat162*>(&u);
    return __bfloat1622float2(b);
}

// A fragment: A[m][kpair] pad P; rows m0+g, m0+g+8; pairs kp+q, kp+4+q
__device__ __forceinline__ void ldA(const unsigned* S, int P, int m0, int kp,
                                    int g, int q,
                                    unsigned& a0, unsigned& a1, unsigned& a2, unsigned& a3) {
    const unsigned* r0 = S + (m0 + g) * P + kp + q;
    const unsigned* r1 = S + (m0 + g + 8) * P + kp + q;
    a0 = r0[0]; a2 = r0[4];
    a1 = r1[0]; a3 = r1[4];
}

// ------------------------------ K0 ------------------------------------------
__global__ void k0_bias(const float* __restrict__ w1, const float* __restrict__ b1,
                        const float* __restrict__ w2) {
    __shared__ float tab[225][4];
    int tid = threadIdx.x;
    if (tid < 225) {
        int a = tid / 15, bb = tid % 15;
        float v0 = (a - 7) * (8.0f / 7.0f), v1 = (bb - 7) * (8.0f / 7.0f);
        float g0 = copysignf(log2f(fabsf(v0) + 1.0f) * (1.0f / 3.0f), v0);
        float g1 = copysignf(log2f(fabsf(v1) + 1.0f) * (1.0f / 3.0f), v1);
        float o0 = 0, o1 = 0, o2 = 0, o3 = 0;
        for (int j = 0; j < 512; j++) {
            float hv = fmaxf(w1[2 * j] * g0 + w1[2 * j + 1] * g1 + b1[j], 0.0f);
            o0 += hv * w2[j];        o1 += hv * w2[512 + j];
            o2 += hv * w2[1024 + j]; o3 += hv * w2[1536 + j];
        }
        tab[tid][0] = o0; tab[tid][1] = o1; tab[tid][2] = o2; tab[tid][3] = o3;
    }
    __syncthreads();
    for (int e = tid; e < 4 * 64 * 64; e += blockDim.x) {
        int h = e >> 12, i = (e >> 6) & 63, j = e & 63;
        int dy = (i >> 3) - (j >> 3) + 7, dx = (i & 7) - (j & 7) + 7;
        float v = tab[dy * 15 + dx][h];
        g_bias16[e] = 16.0f / (1.0f + expf(-v));
    }
}

__device__ __forceinline__ void splitpair(const float* w, unsigned* hi, unsigned* lo, int i) {
    split2(w[2 * i], w[2 * i + 1], hi[i], lo[i]);
}

__global__ void k0_wsplit(const float* __restrict__ qkvw, const float* __restrict__ pw,
                          const float* __restrict__ f1w, const float* __restrict__ f2w) {
    int i = blockIdx.x * 256 + threadIdx.x;
    if (i < 24576)       splitpair(qkvw, g_qkvh, g_qkvl, i);
    else if (i < 32768)  splitpair(pw,  g_pwh,  g_pwl,  i - 24576);
    else if (i < 65536)  splitpair(f1w, g_f1h,  g_f1l,  i - 32768);
    else if (i < 98304)  splitpair(f2w, g_f2h,  g_f2l,  i - 65536);
}

// ------------------------------ K1: attention -------------------------------
// word offsets
#define XHI  0        // [64][68] u32
#define XLO  4352
#define QKVO 8704     // [384][68] f32; reused as Pout [64][132]
#define WHI  34816    // [64][68] u32 weight stage (hi)   | alias ATTN
#define WLO  39168    // [64][68] u32 weight stage (lo)   | alias PT
#define ATTN 34816    // [64][68] f32
#define PTO  39168    // [64][68] f32
#define OHI  43520    // [64][68] u32
#define OLO  47872
#define VTO  52224    // [64][36] f32
#define IQ   54528
#define IK   54592
#define RG   54656
#define K1_SMEM (54720 * 4)

__global__ void __launch_bounds__(256, 1)
k1_attn(const float* __restrict__ x,
        const float* __restrict__ n1w, const float* __restrict__ n1b,
        const float* __restrict__ qb, const float* __restrict__ vb,
        const float* __restrict__ ls, const float* __restrict__ pb) {
    extern __shared__ float sm[];
    unsigned* smu = (unsigned*)sm;
    int tid = threadIdx.x;
    int wid = tid >> 5, lane = tid & 31;
    int g = lane >> 2, q = lane & 3;
    int b = blockIdx.x >> 8, widx = blockIdx.x & 255;
    int wy = widx >> 4, wx = widx & 15;

    // phase 0: gather shifted window, split to bf16 pairs [t][cpair]
    {
        const float* xb = x + (size_t)b * 128 * HW;
#pragma unroll
        for (int it = 0; it < 16; it++) {
            int idx = it * 256 + tid;
            int t = idx & 63, cp = idx >> 6;
            int ti = t >> 3, tj = t & 7;
            int hh = (wy * 8 + ti + 4) & 127;
            int ww = (wx * 8 + tj + 4) & 127;
            const float* p = xb + (size_t)(2 * cp) * HW + hh * 128 + ww;
            float v0 = p[0], v1 = p[HW];
            split2(v0, v1, smu[XHI + t * 68 + cp], smu[XLO + t * 68 + cp]);
        }
        if (tid < 64) {
            int ti = tid >> 3, tj = tid & 7;
            int hs = wy * 8 + ti, ws = wx * 8 + tj;
            int hr = hs < 120 ? 0 : (hs < 124 ? 1 : 2);
            int wr = ws < 120 ? 0 : (ws < 124 ? 1 : 2);
            sm[RG + tid] = (float)(hr * 3 + wr);
        }
    }

    int mi = wid & 3, nh = wid >> 2;
    int m0 = mi * 16;

    // phase 1: QKV GEMM, 6 chunks of 64 cols, split-bf16 3-term mma
    for (int ch = 0; ch < 6; ch++) {
        __syncthreads();
#pragma unroll
        for (int it = 0; it < 16; it++) {
            int p = it * 256 + tid;
            int r = p >> 6, c = p & 63;
            smu[WHI + r * 68 + c] = g_qkvh[(ch * 64 + r) * 64 + c];
            smu[WLO + r * 68 + c] = g_qkvl[(ch * 64 + r) * 64 + c];
        }
        __syncthreads();
        float acc[4][4] = {};
#pragma unroll
        for (int ks = 0; ks < 8; ks++) {
            int kp = ks * 8;
            unsigned ah0, ah1, ah2, ah3, al0, al1, al2, al3;
            ldA(smu + XHI, 68, m0, kp, g, q, ah0, ah1, ah2, ah3);
            ldA(smu + XLO, 68, m0, kp, g, q, al0, al1, al2, al3);
#pragma unroll
            for (int t = 0; t < 4; t++) {
                int n0 = nh * 32 + t * 8;
                unsigned bh0 = smu[WHI + (n0 + g) * 68 + kp + q];
                unsigned bh1 = smu[WHI + (n0 + g) * 68 + kp + 4 + q];
                unsigned bl0 = smu[WLO + (n0 + g) * 68 + kp + q];
                unsigned bl1 = smu[WLO + (n0 + g) * 68 + kp + 4 + q];
                mma_bf16(acc[t], ah0, ah1, ah2, ah3, bh0, bh1);
                mma_bf16(acc[t], ah0, ah1, ah2, ah3, bl0, bl1);
                mma_bf16(acc[t], al0, al1, al2, al3, bh0, bh1);
            }
        }
#pragma unroll
        for (int t = 0; t < 4; t++) {
            int col0 = ch * 64 + nh * 32 + t * 8 + 2 * q;
            float b0c = col0 < 128 ? qb[col0] : (col0 >= 256 ? vb[col0 - 256] : 0.0f);
            float b1c = col0 + 1 < 128 ? qb[col0 + 1] : (col0 + 1 >= 256 ? vb[col0 - 255] : 0.0f);
            sm[QKVO + col0 * 68 + m0 + g]           = acc[t][0] + b0c;
            sm[QKVO + (col0 + 1) * 68 + m0 + g]     = acc[t][1] + b1c;
            sm[QKVO + col0 * 68 + m0 + g + 8]       = acc[t][2] + b0c;
            sm[QKVO + (col0 + 1) * 68 + m0 + g + 8] = acc[t][3] + b1c;
        }
    }

    // phase 2: attention per head (fp32)
    for (int h = 0; h < 4; h++) {
        __syncthreads();
        if (tid < 128) {
            int t = tid & 63;
            int base = (tid < 64 ? 0 : 128) + h * 32;
            float s = 0.f;
#pragma unroll
            for (int d = 0; d < 32; d++) {
                float v = sm[QKVO + (base + d) * 68 + t];
                s += v * v;
            }
            sm[(tid < 64 ? IQ : IK) + t] = 1.0f / fmaxf(sqrtf(s), 1e-12f);
        }
        __syncthreads();
        {
            float scale = __expf(fminf(ls[h], LOG100f));
            int t0 = (tid >> 4) * 4, u0 = (tid & 15) * 4;
            float acc[4][4] = {};
#pragma unroll 4
            for (int d = 0; d < 32; d++) {
                float4 qv = *(const float4*)&sm[QKVO + (h * 32 + d) * 68 + t0];
                float4 kv = *(const float4*)&sm[QKVO + (128 + h * 32 + d) * 68 + u0];
                float q4[4] = {qv.x, qv.y, qv.z, qv.w};
                float k4[4] = {kv.x, kv.y, kv.z, kv.w};
#pragma unroll
                for (int i = 0; i < 4; i++)
#pragma unroll
                    for (int j = 0; j < 4; j++) acc[i][j] += q4[i] * k4[j];
            }
            float iq[4], ik[4], rt[4], ru[4];
#pragma unroll
            for (int i = 0; i < 4; i++) {
                iq[i] = sm[IQ + t0 + i]; ik[i] = sm[IK + u0 + i];
                rt[i] = sm[RG + t0 + i]; ru[i] = sm[RG + u0 + i];
            }
#pragma unroll
            for (int i = 0; i < 4; i++)
#pragma unroll
                for (int j = 0; j < 4; j++) {
                    float msk = (rt[i] != ru[j]) ? -100.0f : 0.0f;
                    float bia = g_bias16[(h * 64 + t0 + i) * 64 + u0 + j];
                    sm[ATTN + (t0 + i) * 68 + u0 + j] =
                        acc[i][j] * iq[i] * ik[j] * scale + bia + msk;
                }
        }
        __syncthreads();
        if (tid < 64) {
            float* row = &sm[ATTN + tid * 68];
            float mx = -1e30f;
            for (int u = 0; u < 64; u++) mx = fmaxf(mx, row[u]);
            float s = 0.f;
            for (int u = 0; u < 64; u++) { float e = __expf(row[u] - mx); row[u] = e; s += e; }
            float inv = 1.0f / s;
            for (int u = 0; u < 64; u++) sm[PTO + u * 68 + tid] = row[u] * inv;
        }
        __syncthreads();
#pragma unroll
        for (int it = 0; it < 8; it++) {
            int p = tid + it * 256;
            int u = p & 63, d = p >> 6;
            sm[VTO + u * 36 + d] = sm[QKVO + (256 + h * 32 + d) * 68 + u];
        }
        __syncthreads();
        if (tid < 128) {
            int tg2 = tid >> 3, dg = tid & 7;
            int tt0 = tg2 * 4, d0 = dg * 4;
            float acc[4][4] = {};
#pragma unroll 2
            for (int u = 0; u < 64; u++) {
                float4 pv = *(const float4*)&sm[PTO + u * 68 + tt0];
                float4 vv = *(const float4*)&sm[VTO + u * 36 + d0];
                float p4[4] = {pv.x, pv.y, pv.z, pv.w};
                float v4[4] = {vv.x, vv.y, vv.z, vv.w};
#pragma unroll
                for (int i = 0; i < 4; i++)
#pragma unroll
                    for (int j = 0; j < 4; j++) acc[i][j] += p4[i] * v4[j];
            }
            int p0 = h * 16 + (d0 >> 1);
#pragma unroll
            for (int i = 0; i < 4; i++) {
                split2(acc[i][0], acc[i][1], smu[OHI + (tt0 + i) * 68 + p0],
                       smu[OLO + (tt0 + i) * 68 + p0]);
                split2(acc[i][2], acc[i][3], smu[OHI + (tt0 + i) * 68 + p0 + 1],
                       smu[OLO + (tt0 + i) * 68 + p0 + 1]);
            }
        }
    }

    // phase 3: proj GEMM (A = O split, B = pw split) -> Pout rows [t][132]
    for (int ch = 0; ch < 2; ch++) {
        __syncthreads();
#pragma unroll
        for (int it = 0; it < 16; it++) {
            int p = it * 256 + tid;
            int r = p >> 6, c = p & 63;
            smu[WHI + r * 68 + c] = g_pwh[(ch * 64 + r) * 64 + c];
            smu[WLO + r * 68 + c] = g_pwl[(ch * 64 + r) * 64 + c];
        }
        __syncthreads();
        float acc[4][4] = {};
#pragma unroll
        for (int ks = 0; ks < 8; ks++) {
            int kp = ks * 8;
            unsigned ah0, ah1, ah2, ah3, al0, al1, al2, al3;
            ldA(smu + OHI, 68, m0, kp, g, q, ah0, ah1, ah2, ah3);
            ldA(smu + OLO, 68, m0, kp, g, q, al0, al1, al2, al3);
#pragma unroll
            for (int t = 0; t < 4; t++) {
                int n0 = nh * 32 + t * 8;
                unsigned bh0 = smu[WHI + (n0 + g) * 68 + kp + q];
                unsigned bh1 = smu[WHI + (n0 + g) * 68 + kp + 4 + q];
                unsigned bl0 = smu[WLO + (n0 + g) * 68 + kp + q];
                unsigned bl1 = smu[WLO + (n0 + g) * 68 + kp + 4 + q];
                mma_bf16(acc[t], ah0, ah1, ah2, ah3, bh0, bh1);
                mma_bf16(acc[t], ah0, ah1, ah2, ah3, bl0, bl1);
                mma_bf16(acc[t], al0, al1, al2, al3, bh0, bh1);
            }
        }
#pragma unroll
        for (int t = 0; t < 4; t++) {
            int col0 = ch * 64 + nh * 32 + t * 8 + 2 * q;
            sm[QKVO + (m0 + g) * 132 + col0]         = acc[t][0] + pb[col0];
            sm[QKVO + (m0 + g) * 132 + col0 + 1]     = acc[t][1] + pb[col0 + 1];
            sm[QKVO + (m0 + g + 8) * 132 + col0]     = acc[t][2] + pb[col0];
            sm[QKVO + (m0 + g + 8) * 132 + col0 + 1] = acc[t][3] + pb[col0 + 1];
        }
    }

    // phase 4: LN + residual -> g_x1
    __syncthreads();
    {
        int t = tid >> 2, ln = tid & 3;
        const float* prow = &sm[QKVO + t * 132];
        int cb = ln * 32;
        float s1 = 0.f, s2 = 0.f;
#pragma unroll 8
        for (int c = 0; c < 32; c++) {
            float v = prow[cb + c];
            s1 += v; s2 += v * v;
        }
        s1 += __shfl_xor_sync(0xffffffffu, s1, 1);
        s2 += __shfl_xor_sync(0xffffffffu, s2, 1);
        s1 += __shfl_xor_sync(0xffffffffu, s1, 2);
        s2 += __shfl_xor_sync(0xffffffffu, s2, 2);
        float mu = s1 * (1.0f / 128.0f);
        float var = fmaxf(s2 * (1.0f / 128.0f) - mu * mu, 0.0f);
        float rs = rsqrtf(var + 1e-5f);
        int ti = t >> 3, tj = t & 7;
        int hh = (wy * 8 + ti + 4) & 127;
        int ww = (wx * 8 + tj + 4) & 127;
        float* dst = &g_x1[((size_t)b * HW + hh * 128 + ww) * 128];
#pragma unroll 8
        for (int cp = 0; cp < 16; cp++) {
            unsigned uh = smu[XHI + t * 68 + (cb >> 1) + cp];
            unsigned ul = smu[XLO + t * 68 + (cb >> 1) + cp];
            float2 fh = unpack2(uh), fl = unpack2(ul);
            int cc = cb + 2 * cp;
            float l0 = (prow[cc] - mu) * rs * n1w[cc] + n1b[cc];
            float l1 = (prow[cc + 1] - mu) * rs * n1w[cc + 1] + n1b[cc + 1];
            dst[cc]     = fh.x + fl.x + l0;
            dst[cc + 1] = fh.y + fl.y + l1;
        }
    }
}

// ------------------------------ K2: MLP -------------------------------------
#define K2XHI 0       // [64][68]
#define K2XLO 4352
#define K2W1H 8704    // [64][68]
#define K2W1L 13056
#define K2HH  17408   // [64][36]
#define K2HL  19712
#define K2W2H 22016   // [128][36]
#define K2W2L 26624
#define K2Y   31232   // [64][133]
#define K2_SMEM (39744 * 4)

__global__ void __launch_bounds__(256, 1)
k2_mlp(const float* __restrict__ n2w, const float* __restrict__ n2b,
       const float* __restrict__ b1, const float* __restrict__ b2,
       float* __restrict__ out) {
    extern __shared__ float sm[];
    unsigned* smu = (unsigned*)sm;
    int tid = threadIdx.x;
    int wid = tid >> 5, lane = tid & 31;
    int g = lane >> 2, q = lane & 3;
    int p0 = blockIdx.x * 64;
    int b = p0 >> 14, h = (p0 >> 7) & 127, w0 = p0 & 127;

    // load + split x1
#pragma unroll
    for (int it = 0; it < 16; it++) {
        int idx = it * 256 + tid;
        int cp = idx & 63, t = idx >> 6;
        float2 v = *(const float2*)&g_x1[((size_t)p0 + t) * 128 + 2 * cp];
        split2(v.x, v.y, smu[K2XHI + t * 68 + cp], smu[K2XLO + t * 68 + cp]);
    }

    int mi = wid & 3, nh = wid >> 2;
    int m0 = mi * 16;
    float acc2[8][4];
#pragma unroll
    for (int t = 0; t < 8; t++)
#pragma unroll
        for (int j = 0; j < 4; j++) acc2[t][j] = 0.f;

    for (int ch = 0; ch < 8; ch++) {
        __syncthreads();
#pragma unroll
        for (int it = 0; it < 16; it++) {   // stage fc1 chunk
            int p = it * 256 + tid;
            int r = p >> 6, c = p & 63;
            smu[K2W1H + r * 68 + c] = g_f1h[(ch * 64 + r) * 64 + c];
            smu[K2W1L + r * 68 + c] = g_f1l[(ch * 64 + r) * 64 + c];
        }
#pragma unroll
        for (int it = 0; it < 16; it++) {   // stage fc2 k-slice
            int p = it * 256 + tid;
            int r = p >> 5, c = p & 31;
            smu[K2W2H + r * 36 + c] = g_f2h[r * 256 + ch * 32 + c];
            smu[K2W2L + r * 36 + c] = g_f2l[r * 256 + ch * 32 + c];
        }
        __syncthreads();
        // fc1 chunk
        float acc[4][4] = {};
#pragma unroll
        for (int ks = 0; ks < 8; ks++) {
            int kp = ks * 8;
            unsigned ah0, ah1, ah2, ah3, al0, al1, al2, al3;
            ldA(smu + K2XHI, 68, m0, kp, g, q, ah0, ah1, ah2, ah3);
            ldA(smu + K2XLO, 68, m0, kp, g, q, al0, al1, al2, al3);
#pragma unroll
            for (int t = 0; t < 4; t++) {
                int n0 = nh * 32 + t * 8;
                unsigned bh0 = smu[K2W1H + (n0 + g) * 68 + kp + q];
                unsigned bh1 = smu[K2W1H + (n0 + g) * 68 + kp + 4 + q];
                unsigned bl0 = smu[K2W1L + (n0 + g) * 68 + kp + q];
                unsigned bl1 = smu[K2W1L + (n0 + g) * 68 + kp + 4 + q];
                mma_bf16(acc[t], ah0, ah1, ah2, ah3, bh0, bh1);
                mma_bf16(acc[t], ah0, ah1, ah2, ah3, bl0, bl1);
                mma_bf16(acc[t], al0, al1, al2, al3, bh0, bh1);
            }
        }
        // silu + split -> H
#pragma unroll
        for (int t = 0; t < 4; t++) {
            int c0 = nh * 32 + t * 8 + 2 * q;
            int col = ch * 64 + c0;
            float v0 = acc[t][0] + b1[col],     v1 = acc[t][1] + b1[col + 1];
            float v2 = acc[t][2] + b1[col],     v3 = acc[t][3] + b1[col + 1];
            v0 = v0 / (1.0f + __expf(-v0));
            v1 = v1 / (1.0f + __expf(-v1));
            v2 = v2 / (1.0f + __expf(-v2));
            v3 = v3 / (1.0f + __expf(-v3));
            int pp = nh * 16 + t * 4 + q;
            split2(v0, v1, smu[K2HH + (m0 + g) * 36 + pp], smu[K2HL + (m0 + g) * 36 + pp]);
            split2(v2, v3, smu[K2HH + (m0 + g + 8) * 36 + pp], smu[K2HL + (m0 + g + 8) * 36 + pp]);
        }
        __syncthreads();
        // fc2 partial (K=64 slice)
#pragma unroll
        for (int ks = 0; ks < 4; ks++) {
            int kp = ks * 8;
            unsigned ah0, ah1, ah2, ah3, al0, al1, al2, al3;
            ldA(smu + K2HH, 36, m0, kp, g, q, ah0, ah1, ah2, ah3);
            ldA(smu + K2HL, 36, m0, kp, g, q, al0, al1, al2, al3);
#pragma unroll
            for (int t = 0; t < 8; t++) {
                int n0 = nh * 64 + t * 8;
                unsigned bh0 = smu[K2W2H + (n0 + g) * 36 + kp + q];
                unsigned bh1 = smu[K2W2H + (n0 + g) * 36 + kp + 4 + q];
                unsigned bl0 = smu[K2W2L + (n0 + g) * 36 + kp + q];
                unsigned bl1 = smu[K2W2L + (n0 + g) * 36 + kp + 4 + q];
                mma_bf16(acc2[t], ah0, ah1, ah2, ah3, bh0, bh1);
                mma_bf16(acc2[t], ah0, ah1, ah2, ah3, bl0, bl1);
                mma_bf16(acc2[t], al0, al1, al2, al3, bh0, bh1);
            }
        }
    }
    // Y = fc2 out + bias
#pragma unroll
    for (int t = 0; t < 8; t++) {
        int col = nh * 64 + t * 8 + 2 * q;
        sm[K2Y + (m0 + g) * 133 + col]         = acc2[t][0] + b2[col];
        sm[K2Y + (m0 + g) * 133 + col + 1]     = acc2[t][1] + b2[col + 1];
        sm[K2Y + (m0 + g + 8) * 133 + col]     = acc2[t][2] + b2[col];
        sm[K2Y + (m0 + g + 8) * 133 + col + 1] = acc2[t][3] + b2[col + 1];
    }
    __syncthreads();
    // LN + residual (x1 = hi + lo)
    {
        int t = tid >> 2, ln = tid & 3;
        float* yrow = &sm[K2Y + t * 133];
        int cb = ln * 32;
        float s1 = 0.f, s2 = 0.f;
#pragma unroll 8
        for (int c = 0; c < 32; c++) {
            float v = yrow[cb + c];
            s1 += v; s2 += v * v;
        }
        s1 += __shfl_xor_sync(0xffffffffu, s1, 1);
        s2 += __shfl_xor_sync(0xffffffffu, s2, 1);
        s1 += __shfl_xor_sync(0xffffffffu, s1, 2);
        s2 += __shfl_xor_sync(0xffffffffu, s2, 2);
        float mu = s1 * (1.0f / 128.0f);
        float var = fmaxf(s2 * (1.0f / 128.0f) - mu * mu, 0.0f);
        float rs = rsqrtf(var + 1e-5f);
#pragma unroll 8
        for (int cp = 0; cp < 16; cp++) {
            unsigned uh = smu[K2XHI + t * 68 + (cb >> 1) + cp];
            unsigned ul = smu[K2XLO + t * 68 + (cb >> 1) + cp];
            float2 fh = unpack2(uh), fl = unpack2(ul);
            int cc = cb + 2 * cp;
            float l0 = (yrow[cc] - mu) * rs * n2w[cc] + n2b[cc];
            float l1 = (yrow[cc + 1] - mu) * rs * n2w[cc + 1] + n2b[cc + 1];
            yrow[cc]     = fh.x + fl.x + l0;
            yrow[cc + 1] = fh.y + fl.y + l1;
        }
    }
    __syncthreads();
    // transposed store -> NCHW
    {
        float* ob = out + (size_t)b * 128 * HW + h * 128 + w0;
#pragma unroll
        for (int it = 0; it < 32; it++) {
            int idx = it * 256 + tid;
            int c = idx >> 6, ww = idx & 63;
            ob[(size_t)c * HW + ww] = sm[K2Y + ww * 133 + c];
        }
    }
}

// ------------------------------ launch --------------------------------------
extern "C" void kernel_launch(void* const* d_in, const int* in_sizes, int n_in,
                              void* d_out, int out_size) {
    const float* x    = (const float*)d_in[0];
    const float* n1w  = (const float*)d_in[1];
    const float* n1b  = (const float*)d_in[2];
    const float* qkvw = (const float*)d_in[3];
    const float* qb   = (const float*)d_in[4];
    const float* vb   = (const float*)d_in[5];
    const float* ls   = (const float*)d_in[6];
    const float* cw1  = (const float*)d_in[7];
    const float* cb1  = (const float*)d_in[8];
    const float* cw2  = (const float*)d_in[9];
    const float* pw   = (const float*)d_in[10];
    const float* pb   = (const float*)d_in[11];
    const float* n2w  = (const float*)d_in[12];
    const float* n2b  = (const float*)d_in[13];
    const float* f1w  = (const float*)d_in[14];
    const float* f1b  = (const float*)d_in[15];
    const float* f2w  = (const float*)d_in[16];
    const float* f2b  = (const float*)d_in[17];
    float* out = (float*)d_out;

    cudaFuncSetAttribute(k1_attn, cudaFuncAttributeMaxDynamicSharedMemorySize, K1_SMEM);
    cudaFuncSetAttribute(k2_mlp,  cudaFuncAttributeMaxDynamicSharedMemorySize, K2_SMEM);

    k0_bias<<<1, 256>>>(cw1, cb1, cw2);
    k0_wsplit<<<384, 256>>>(qkvw, pw, f1w, f2w);
    k1_attn<<<4096, 256, K1_SMEM>>>(x, n1w, n1b, qb, vb, ls, pb);
    k2_mlp<<<4096, 256, K2_SMEM>>>(n2w, n2b, f1b, f2b, out);
}

// round 6
// speedup vs baseline: 2.3698x; 1.1146x over previous
#include <cuda_runtime.h>
#include <cuda_bf16.h>
#include <math.h>

#define HW 16384
#define LOG100f 4.605170185988092f

__device__ float g_x1[16u * HW * 128u];   // x1 token-major [tok][128]
__device__ float g_bias16[4 * 64 * 64];   // 16*sigmoid(cpb bias)
// pre-split weights, bf16 pairs packed in u32 along K
__device__ unsigned g_qkvh[24576], g_qkvl[24576];   // [384][64]
__device__ unsigned g_pwh[8192],   g_pwl[8192];     // [128][64]
__device__ unsigned g_f1h[32768],  g_f1l[32768];    // [512][64]
__device__ unsigned g_f2h[32768],  g_f2l[32768];    // [128][256]

// ---------------------------------------------------------------------------
__device__ __forceinline__ void mma_bf16(float d[4], unsigned a0, unsigned a1,
                                         unsigned a2, unsigned a3,
                                         unsigned b0, unsigned b1) {
    asm volatile(
        "mma.sync.aligned.m16n8k16.row.col.f32.bf16.bf16.f32 "
        "{%0,%1,%2,%3},{%4,%5,%6,%7},{%8,%9},{%0,%1,%2,%3};"
        : "+f"(d[0]), "+f"(d[1]), "+f"(d[2]), "+f"(d[3])
        : "r"(a0), "r"(a1), "r"(a2), "r"(a3), "r"(b0), "r"(b1));
}

// ldmatrix x4: rows r0+(lane&15), pair offset kp + 4*(lane>>4), pitch P (u32 words)
__device__ __forceinline__ void ldsm4(const unsigned* base, int P, int r0, int kp,
                                      unsigned& o0, unsigned& o1, unsigned& o2, unsigned& o3) {
    int lane = threadIdx.x & 31;
    const unsigned* p = base + (r0 + (lane & 15)) * P + kp + ((lane >> 4) << 2);
    unsigned a = (unsigned)__cvta_generic_to_shared(p);
    asm volatile("ldmatrix.sync.aligned.m8n8.x4.shared.b16 {%0,%1,%2,%3}, [%4];"
                 : "=r"(o0), "=r"(o1), "=r"(o2), "=r"(o3) : "r"(a));
}

__device__ __forceinline__ void split2(float v0, float v1, unsigned& hi, unsigned& lo) {
    __nv_bfloat16 h0 = __float2bfloat16(v0);
    __nv_bfloat16 h1 = __float2bfloat16(v1);
    float r0 = v0 - __bfloat162float(h0);
    float r1 = v1 - __bfloat162float(h1);
    __nv_bfloat16 l0 = __float2bfloat16(r0);
    __nv_bfloat16 l1 = __float2bfloat16(r1);
    hi = (unsigned)__bfloat16_as_ushort(h0) | ((unsigned)__bfloat16_as_ushort(h1) << 16);
    lo = (unsigned)__bfloat16_as_ushort(l0) | ((unsigned)__bfloat16_as_ushort(l1) << 16);
}

__device__ __forceinline__ float2 unpack2(unsigned u) {
    __nv_bfloat162 b = *reinterpret_cast<__nv_bfloat162*>(&u);
    return __bfloat1622float2(b);
}

// ------------------------------ K0 ------------------------------------------
__global__ void k0_bias(const float* __restrict__ w1, const float* __restrict__ b1,
                        const float* __restrict__ w2) {
    __shared__ float tab[225][4];
    int tid = threadIdx.x;
    if (tid < 225) {
        int a = tid / 15, bb = tid % 15;
        float v0 = (a - 7) * (8.0f / 7.0f), v1 = (bb - 7) * (8.0f / 7.0f);
        float g0 = copysignf(log2f(fabsf(v0) + 1.0f) * (1.0f / 3.0f), v0);
        float g1 = copysignf(log2f(fabsf(v1) + 1.0f) * (1.0f / 3.0f), v1);
        float o0 = 0, o1 = 0, o2 = 0, o3 = 0;
        for (int j = 0; j < 512; j++) {
            float hv = fmaxf(w1[2 * j] * g0 + w1[2 * j + 1] * g1 + b1[j], 0.0f);
            o0 += hv * w2[j];        o1 += hv * w2[512 + j];
            o2 += hv * w2[1024 + j]; o3 += hv * w2[1536 + j];
        }
        tab[tid][0] = o0; tab[tid][1] = o1; tab[tid][2] = o2; tab[tid][3] = o3;
    }
    __syncthreads();
    for (int e = tid; e < 4 * 64 * 64; e += blockDim.x) {
        int h = e >> 12, i = (e >> 6) & 63, j = e & 63;
        int dy = (i >> 3) - (j >> 3) + 7, dx = (i & 7) - (j & 7) + 7;
        float v = tab[dy * 15 + dx][h];
        g_bias16[e] = 16.0f / (1.0f + expf(-v));
    }
}

__device__ __forceinline__ void splitpair(const float* w, unsigned* hi, unsigned* lo, int i) {
    split2(w[2 * i], w[2 * i + 1], hi[i], lo[i]);
}

__global__ void k0_wsplit(const float* __restrict__ qkvw, const float* __restrict__ pw,
                          const float* __restrict__ f1w, const float* __restrict__ f2w) {
    int i = blockIdx.x * 256 + threadIdx.x;
    if (i < 24576)       splitpair(qkvw, g_qkvh, g_qkvl, i);
    else if (i < 32768)  splitpair(pw,  g_pwh,  g_pwl,  i - 24576);
    else if (i < 65536)  splitpair(f1w, g_f1h,  g_f1l,  i - 32768);
    else if (i < 98304)  splitpair(f2w, g_f2h,  g_f2l,  i - 65536);
}

// ------------------------------ K1: attention -------------------------------
// word offsets
#define XHI  0        // [64][68] u32  (A operand, token rows)
#define XLO  4352
#define QKVO 8704     // [384][68] f32 ; reused: Pout rows [64][132]
#define WHI  34816    // [64][68] u32 weight stage hi
#define WLO  39168    // [64][68] u32 weight stage lo
// attention-scratch aliases inside 34816..44288
#define QHI  34816    // [64][20]
#define QLO  36096
#define KHI  37376
#define KLO  38656    // ends 39936
#define ATTN 39936    // [64][68] f32, ends 44288
#define PHI  34816    // [64][36] (over dead Q/K splits)
#define PLO  37120    // ends 39424
#define VHI  39936    // [32][36] (over dead ATTN)
#define VLO  41088    // ends 42240
#define OHI  44288    // [64][68] u32
#define OLO  48640
#define IQ   52992
#define IK   53056
#define RG   53120
#define K1_SMEM (53184 * 4)

__global__ void __launch_bounds__(256, 1)
k1_attn(const float* __restrict__ x,
        const float* __restrict__ n1w, const float* __restrict__ n1b,
        const float* __restrict__ qb, const float* __restrict__ vb,
        const float* __restrict__ ls, const float* __restrict__ pb) {
    extern __shared__ float sm[];
    unsigned* smu = (unsigned*)sm;
    int tid = threadIdx.x;
    int wid = tid >> 5, lane = tid & 31;
    int g = lane >> 2, q = lane & 3;
    int b = blockIdx.x >> 8, widx = blockIdx.x & 255;
    int wy = widx >> 4, wx = widx & 15;

    // phase 0: gather shifted window, split to bf16 pairs [t][cpair]
    {
        const float* xb = x + (size_t)b * 128 * HW;
#pragma unroll
        for (int it = 0; it < 16; it++) {
            int idx = it * 256 + tid;
            int t = idx & 63, cp = idx >> 6;
            int ti = t >> 3, tj = t & 7;
            int hh = (wy * 8 + ti + 4) & 127;
            int ww = (wx * 8 + tj + 4) & 127;
            const float* p = xb + (size_t)(2 * cp) * HW + hh * 128 + ww;
            float v0 = p[0], v1 = p[HW];
            split2(v0, v1, smu[XHI + t * 68 + cp], smu[XLO + t * 68 + cp]);
        }
        if (tid < 64) {
            int ti = tid >> 3, tj = tid & 7;
            int hs = wy * 8 + ti, ws = wx * 8 + tj;
            int hr = hs < 120 ? 0 : (hs < 124 ? 1 : 2);
            int wr = ws < 120 ? 0 : (ws < 124 ? 1 : 2);
            sm[RG + tid] = (float)(hr * 3 + wr);
        }
    }

    int mi = wid & 3, nh = wid >> 2;
    int m0 = mi * 16;
    int n0w = nh * 32;

    // phase 1: QKV GEMM, 6 chunks of 64 cols, split-bf16 3-term mma
    for (int ch = 0; ch < 6; ch++) {
        __syncthreads();
#pragma unroll
        for (int it = 0; it < 16; it++) {
            int p = it * 256 + tid;
            int r = p >> 6, c = p & 63;
            smu[WHI + r * 68 + c] = g_qkvh[(ch * 64 + r) * 64 + c];
            smu[WLO + r * 68 + c] = g_qkvl[(ch * 64 + r) * 64 + c];
        }
        __syncthreads();
        float acc[4][4] = {};
#pragma unroll
        for (int ks = 0; ks < 8; ks++) {
            int kp = ks * 8;
            unsigned ah0, ah1, ah2, ah3, al0, al1, al2, al3;
            ldsm4(smu + XHI, 68, m0, kp, ah0, ah1, ah2, ah3);
            ldsm4(smu + XLO, 68, m0, kp, al0, al1, al2, al3);
#pragma unroll
            for (int hf = 0; hf < 2; hf++) {
                unsigned bh0, bh1, bh2, bh3, bl0, bl1, bl2, bl3;
                ldsm4(smu + WHI, 68, n0w + 16 * hf, kp, bh0, bh1, bh2, bh3);
                ldsm4(smu + WLO, 68, n0w + 16 * hf, kp, bl0, bl1, bl2, bl3);
                mma_bf16(acc[2 * hf],     ah0, ah1, ah2, ah3, bh0, bh2);
                mma_bf16(acc[2 * hf],     ah0, ah1, ah2, ah3, bl0, bl2);
                mma_bf16(acc[2 * hf],     al0, al1, al2, al3, bh0, bh2);
                mma_bf16(acc[2 * hf + 1], ah0, ah1, ah2, ah3, bh1, bh3);
                mma_bf16(acc[2 * hf + 1], ah0, ah1, ah2, ah3, bl1, bl3);
                mma_bf16(acc[2 * hf + 1], al0, al1, al2, al3, bh1, bh3);
            }
        }
#pragma unroll
        for (int nt = 0; nt < 4; nt++) {
            int col0 = ch * 64 + n0w + nt * 8 + 2 * q;
            float b0c = col0 < 128 ? qb[col0] : (col0 >= 256 ? vb[col0 - 256] : 0.0f);
            float b1c = col0 + 1 < 128 ? qb[col0 + 1] : (col0 + 1 >= 256 ? vb[col0 - 255] : 0.0f);
            sm[QKVO + col0 * 68 + m0 + g]           = acc[nt][0] + b0c;
            sm[QKVO + (col0 + 1) * 68 + m0 + g]     = acc[nt][1] + b1c;
            sm[QKVO + col0 * 68 + m0 + g + 8]       = acc[nt][2] + b0c;
            sm[QKVO + (col0 + 1) * 68 + m0 + g + 8] = acc[nt][3] + b1c;
        }
    }

    // phase 2: attention per head, fully MMA
    for (int h = 0; h < 4; h++) {
        __syncthreads();
        // inverse norms: 2 threads per row, 128 rows (q then k)
        {
            int r = tid >> 1, half = tid & 1;
            int t = r & 63;
            int cbase = (r < 64 ? 0 : 128) + h * 32 + half * 16;
            float s = 0.f;
#pragma unroll
            for (int d = 0; d < 16; d++) {
                float v = sm[QKVO + (cbase + d) * 68 + t];
                s += v * v;
            }
            s += __shfl_xor_sync(0xffffffffu, s, 1);
            if (half == 0)
                sm[(r < 64 ? IQ : IK) + t] = 1.0f / fmaxf(sqrtf(s), 1e-12f);
        }
        __syncthreads();
        // normalize + split Q,K -> [t][dpair] pitch 20 (norms folded in HERE)
#pragma unroll
        for (int it = 0; it < 8; it++) {
            int idx = it * 256 + tid;
            int t = idx & 63, p = (idx >> 6) & 15, m = idx >> 10;
            int cbase = (m ? 128 : 0) + h * 32 + 2 * p;
            float inv = sm[(m ? IK : IQ) + t];
            float v0 = sm[QKVO + cbase * 68 + t] * inv;
            float v1 = sm[QKVO + (cbase + 1) * 68 + t] * inv;
            split2(v0, v1, smu[(m ? KHI : QHI) + t * 20 + p],
                   smu[(m ? KLO : QLO) + t * 20 + p]);
        }
        __syncthreads();
        // logits MMA: 64x64, warp tile m16 x n32
        {
            float scale = __expf(fminf(ls[h], LOG100f));
            float acc[4][4] = {};
#pragma unroll
            for (int ks = 0; ks < 2; ks++) {
                int kp = ks * 8;
                unsigned ah0, ah1, ah2, ah3, al0, al1, al2, al3;
                ldsm4(smu + QHI, 20, m0, kp, ah0, ah1, ah2, ah3);
                ldsm4(smu + QLO, 20, m0, kp, al0, al1, al2, al3);
#pragma unroll
                for (int hf = 0; hf < 2; hf++) {
                    unsigned bh0, bh1, bh2, bh3, bl0, bl1, bl2, bl3;
                    ldsm4(smu + KHI, 20, n0w + 16 * hf, kp, bh0, bh1, bh2, bh3);
                    ldsm4(smu + KLO, 20, n0w + 16 * hf, kp, bl0, bl1, bl2, bl3);
                    mma_bf16(acc[2 * hf],     ah0, ah1, ah2, ah3, bh0, bh2);
                    mma_bf16(acc[2 * hf],     ah0, ah1, ah2, ah3, bl0, bl2);
                    mma_bf16(acc[2 * hf],     al0, al1, al2, al3, bh0, bh2);
                    mma_bf16(acc[2 * hf + 1], ah0, ah1, ah2, ah3, bh1, bh3);
                    mma_bf16(acc[2 * hf + 1], ah0, ah1, ah2, ah3, bl1, bl3);
                    mma_bf16(acc[2 * hf + 1], al0, al1, al2, al3, bh1, bh3);
                }
            }
            // NOTE: q,k already normalized before MMA -> epilogue is scale+bias+mask only
            int row0 = m0 + g, row1 = row0 + 8;
            float rt0 = sm[RG + row0], rt1 = sm[RG + row1];
#pragma unroll
            for (int nt = 0; nt < 4; nt++) {
                int col = n0w + nt * 8 + 2 * q;
                float ru0 = sm[RG + col], ru1 = sm[RG + col + 1];
                float2 b0v = *(const float2*)&g_bias16[(h * 64 + row0) * 64 + col];
                float2 b1v = *(const float2*)&g_bias16[(h * 64 + row1) * 64 + col];
                sm[ATTN + row0 * 68 + col]     = acc[nt][0] * scale + b0v.x + (rt0 != ru0 ? -100.f : 0.f);
                sm[ATTN + row0 * 68 + col + 1] = acc[nt][1] * scale + b0v.y + (rt0 != ru1 ? -100.f : 0.f);
                sm[ATTN + row1 * 68 + col]     = acc[nt][2] * scale + b1v.x + (rt1 != ru0 ? -100.f : 0.f);
                sm[ATTN + row1 * 68 + col + 1] = acc[nt][3] * scale + b1v.y + (rt1 != ru1 ? -100.f : 0.f);
            }
        }
        __syncthreads();
        // softmax (4 threads/row) -> P split [t][upair] pitch 36
        {
            int t = tid >> 2, ln = tid & 3;
            const float* row = &sm[ATTN + t * 68 + ln * 16];
            float e[16];
            float mx = -1e30f;
#pragma unroll
            for (int i = 0; i < 16; i++) { e[i] = row[i]; mx = fmaxf(mx, e[i]); }
            mx = fmaxf(mx, __shfl_xor_sync(0xffffffffu, mx, 1));
            mx = fmaxf(mx, __shfl_xor_sync(0xffffffffu, mx, 2));
            float s = 0.f;
#pragma unroll
            for (int i = 0; i < 16; i++) { e[i] = __expf(e[i] - mx); s += e[i]; }
            s += __shfl_xor_sync(0xffffffffu, s, 1);
            s += __shfl_xor_sync(0xffffffffu, s, 2);
            float inv = 1.0f / s;
#pragma unroll
            for (int i = 0; i < 8; i++)
                split2(e[2 * i] * inv, e[2 * i + 1] * inv,
                       smu[PHI + t * 36 + ln * 8 + i], smu[PLO + t * 36 + ln * 8 + i]);
        }
        __syncthreads();
        // V split -> [d][upair] pitch 36 (over dead ATTN)
#pragma unroll
        for (int it = 0; it < 4; it++) {
            int idx = it * 256 + tid;
            int u = idx & 31, d = idx >> 5;
            float2 v = *(const float2*)&sm[QKVO + (256 + h * 32 + d) * 68 + 2 * u];
            split2(v.x, v.y, smu[VHI + d * 36 + u], smu[VLO + d * 36 + u]);
        }
        __syncthreads();
        // PV MMA: out [64 t][32 d], warp tile m16 x n16
        {
            int n0v = nh * 16;
            float acc[2][4] = {};
#pragma unroll
            for (int ks = 0; ks < 4; ks++) {
                int kp = ks * 8;
                unsigned ah0, ah1, ah2, ah3, al0, al1, al2, al3;
                ldsm4(smu + PHI, 36, m0, kp, ah0, ah1, ah2, ah3);
                ldsm4(smu + PLO, 36, m0, kp, al0, al1, al2, al3);
                unsigned bh0, bh1, bh2, bh3, bl0, bl1, bl2, bl3;
                ldsm4(smu + VHI, 36, n0v, kp, bh0, bh1, bh2, bh3);
                ldsm4(smu + VLO, 36, n0v, kp, bl0, bl1, bl2, bl3);
                mma_bf16(acc[0], ah0, ah1, ah2, ah3, bh0, bh2);
                mma_bf16(acc[0], ah0, ah1, ah2, ah3, bl0, bl2);
                mma_bf16(acc[0], al0, al1, al2, al3, bh0, bh2);
                mma_bf16(acc[1], ah0, ah1, ah2, ah3, bh1, bh3);
                mma_bf16(acc[1], ah0, ah1, ah2, ah3, bl1, bl3);
                mma_bf16(acc[1], al0, al1, al2, al3, bh1, bh3);
            }
#pragma unroll
            for (int nt = 0; nt < 2; nt++) {
                int pr = h * 16 + ((n0v + nt * 8) >> 1) + q;
                split2(acc[nt][0], acc[nt][1],
                       smu[OHI + (m0 + g) * 68 + pr], smu[OLO + (m0 + g) * 68 + pr]);
                split2(acc[nt][2], acc[nt][3],
                       smu[OHI + (m0 + g + 8) * 68 + pr], smu[OLO + (m0 + g + 8) * 68 + pr]);
            }
        }
    }

    // phase 3: proj GEMM -> Pout rows [t][132] in QKVO region
    for (int ch = 0; ch < 2; ch++) {
        __syncthreads();
#pragma unroll
        for (int it = 0; it < 16; it++) {
            int p = it * 256 + tid;
            int r = p >> 6, c = p & 63;
            smu[WHI + r * 68 + c] = g_pwh[(ch * 64 + r) * 64 + c];
            smu[WLO + r * 68 + c] = g_pwl[(ch * 64 + r) * 64 + c];
        }
        __syncthreads();
        float acc[4][4] = {};
#pragma unroll
        for (int ks = 0; ks < 8; ks++) {
            int kp = ks * 8;
            unsigned ah0, ah1, ah2, ah3, al0, al1, al2, al3;
            ldsm4(smu + OHI, 68, m0, kp, ah0, ah1, ah2, ah3);
            ldsm4(smu + OLO, 68, m0, kp, al0, al1, al2, al3);
#pragma unroll
            for (int hf = 0; hf < 2; hf++) {
                unsigned bh0, bh1, bh2, bh3, bl0, bl1, bl2, bl3;
                ldsm4(smu + WHI, 68, n0w + 16 * hf, kp, bh0, bh1, bh2, bh3);
                ldsm4(smu + WLO, 68, n0w + 16 * hf, kp, bl0, bl1, bl2, bl3);
                mma_bf16(acc[2 * hf],     ah0, ah1, ah2, ah3, bh0, bh2);
                mma_bf16(acc[2 * hf],     ah0, ah1, ah2, ah3, bl0, bl2);
                mma_bf16(acc[2 * hf],     al0, al1, al2, al3, bh0, bh2);
                mma_bf16(acc[2 * hf + 1], ah0, ah1, ah2, ah3, bh1, bh3);
                mma_bf16(acc[2 * hf + 1], ah0, ah1, ah2, ah3, bl1, bl3);
                mma_bf16(acc[2 * hf + 1], al0, al1, al2, al3, bh1, bh3);
            }
        }
#pragma unroll
        for (int nt = 0; nt < 4; nt++) {
            int col0 = ch * 64 + n0w + nt * 8 + 2 * q;
            sm[QKVO + (m0 + g) * 132 + col0]         = acc[nt][0] + pb[col0];
            sm[QKVO + (m0 + g) * 132 + col0 + 1]     = acc[nt][1] + pb[col0 + 1];
            sm[QKVO + (m0 + g + 8) * 132 + col0]     = acc[nt][2] + pb[col0];
            sm[QKVO + (m0 + g + 8) * 132 + col0 + 1] = acc[nt][3] + pb[col0 + 1];
        }
    }

    // phase 4: LN + residual -> g_x1
    __syncthreads();
    {
        int t = tid >> 2, ln = tid & 3;
        const float* prow = &sm[QKVO + t * 132];
        int cb = ln * 32;
        float s1 = 0.f, s2 = 0.f;
#pragma unroll 8
        for (int c = 0; c < 32; c++) {
            float v = prow[cb + c];
            s1 += v; s2 += v * v;
        }
        s1 += __shfl_xor_sync(0xffffffffu, s1, 1);
        s2 += __shfl_xor_sync(0xffffffffu, s2, 1);
        s1 += __shfl_xor_sync(0xffffffffu, s1, 2);
        s2 += __shfl_xor_sync(0xffffffffu, s2, 2);
        float mu = s1 * (1.0f / 128.0f);
        float var = fmaxf(s2 * (1.0f / 128.0f) - mu * mu, 0.0f);
        float rs = rsqrtf(var + 1e-5f);
        int ti = t >> 3, tj = t & 7;
        int hh = (wy * 8 + ti + 4) & 127;
        int ww = (wx * 8 + tj + 4) & 127;
        float* dst = &g_x1[((size_t)b * HW + hh * 128 + ww) * 128];
#pragma unroll 8
        for (int cp = 0; cp < 16; cp++) {
            unsigned uh = smu[XHI + t * 68 + (cb >> 1) + cp];
            unsigned ul = smu[XLO + t * 68 + (cb >> 1) + cp];
            float2 fh = unpack2(uh), fl = unpack2(ul);
            int cc = cb + 2 * cp;
            float l0 = (prow[cc] - mu) * rs * n1w[cc] + n1b[cc];
            float l1 = (prow[cc + 1] - mu) * rs * n1w[cc + 1] + n1b[cc + 1];
            dst[cc]     = fh.x + fl.x + l0;
            dst[cc + 1] = fh.y + fl.y + l1;
        }
    }
}

// ------------------------------ K2: MLP -------------------------------------
#define K2XHI 0       // [64][68]
#define K2XLO 4352
#define K2W1H 8704    // [64][68]
#define K2W1L 13056
#define K2HH  17408   // [64][36]
#define K2HL  19712
#define K2W2H 22016   // [128][36]
#define K2W2L 26624
#define K2Y   31232   // [64][133]
#define K2_SMEM (39744 * 4)

__global__ void __launch_bounds__(256, 1)
k2_mlp(const float* __restrict__ n2w, const float* __restrict__ n2b,
       const float* __restrict__ b1, const float* __restrict__ b2,
       float* __restrict__ out) {
    extern __shared__ float sm[];
    unsigned* smu = (unsigned*)sm;
    int tid = threadIdx.x;
    int wid = tid >> 5, lane = tid & 31;
    int g = lane >> 2, q = lane & 3;
    int p0 = blockIdx.x * 64;
    int b = p0 >> 14, h = (p0 >> 7) & 127, w0 = p0 & 127;

    // load + split x1
#pragma unroll
    for (int it = 0; it < 16; it++) {
        int idx = it * 256 + tid;
        int cp = idx & 63, t = idx >> 6;
        float2 v = *(const float2*)&g_x1[((size_t)p0 + t) * 128 + 2 * cp];
        split2(v.x, v.y, smu[K2XHI + t * 68 + cp], smu[K2XLO + t * 68 + cp]);
    }

    int mi = wid & 3, nh = wid >> 2;
    int m0 = mi * 16;
    int n0w = nh * 32;
    float acc2[8][4];
#pragma unroll
    for (int t = 0; t < 8; t++)
#pragma unroll
        for (int j = 0; j < 4; j++) acc2[t][j] = 0.f;

    for (int ch = 0; ch < 8; ch++) {
        __syncthreads();
#pragma unroll
        for (int it = 0; it < 16; it++) {   // stage fc1 chunk
            int p = it * 256 + tid;
            int r = p >> 6, c = p & 63;
            smu[K2W1H + r * 68 + c] = g_f1h[(ch * 64 + r) * 64 + c];
            smu[K2W1L + r * 68 + c] = g_f1l[(ch * 64 + r) * 64 + c];
        }
#pragma unroll
        for (int it = 0; it < 16; it++) {   // stage fc2 k-slice
            int p = it * 256 + tid;
            int r = p >> 5, c = p & 31;
            smu[K2W2H + r * 36 + c] = g_f2h[r * 256 + ch * 32 + c];
            smu[K2W2L + r * 36 + c] = g_f2l[r * 256 + ch * 32 + c];
        }
        __syncthreads();
        // fc1 chunk
        float acc[4][4] = {};
#pragma unroll
        for (int ks = 0; ks < 8; ks++) {
            int kp = ks * 8;
            unsigned ah0, ah1, ah2, ah3, al0, al1, al2, al3;
            ldsm4(smu + K2XHI, 68, m0, kp, ah0, ah1, ah2, ah3);
            ldsm4(smu + K2XLO, 68, m0, kp, al0, al1, al2, al3);
#pragma unroll
            for (int hf = 0; hf < 2; hf++) {
                unsigned bh0, bh1, bh2, bh3, bl0, bl1, bl2, bl3;
                ldsm4(smu + K2W1H, 68, n0w + 16 * hf, kp, bh0, bh1, bh2, bh3);
                ldsm4(smu + K2W1L, 68, n0w + 16 * hf, kp, bl0, bl1, bl2, bl3);
                mma_bf16(acc[2 * hf],     ah0, ah1, ah2, ah3, bh0, bh2);
                mma_bf16(acc[2 * hf],     ah0, ah1, ah2, ah3, bl0, bl2);
                mma_bf16(acc[2 * hf],     al0, al1, al2, al3, bh0, bh2);
                mma_bf16(acc[2 * hf + 1], ah0, ah1, ah2, ah3, bh1, bh3);
                mma_bf16(acc[2 * hf + 1], ah0, ah1, ah2, ah3, bl1, bl3);
                mma_bf16(acc[2 * hf + 1], al0, al1, al2, al3, bh1, bh3);
            }
        }
        // silu + split -> H [t][hpair] pitch 36
#pragma unroll
        for (int nt = 0; nt < 4; nt++) {
            int c0 = n0w + nt * 8 + 2 * q;
            int col = ch * 64 + c0;
            float v0 = acc[nt][0] + b1[col],     v1 = acc[nt][1] + b1[col + 1];
            float v2 = acc[nt][2] + b1[col],     v3 = acc[nt][3] + b1[col + 1];
            v0 = v0 / (1.0f + __expf(-v0));
            v1 = v1 / (1.0f + __expf(-v1));
            v2 = v2 / (1.0f + __expf(-v2));
            v3 = v3 / (1.0f + __expf(-v3));
            int pp = (c0 >> 1);
            split2(v0, v1, smu[K2HH + (m0 + g) * 36 + pp], smu[K2HL + (m0 + g) * 36 + pp]);
            split2(v2, v3, smu[K2HH + (m0 + g + 8) * 36 + pp], smu[K2HL + (m0 + g + 8) * 36 + pp]);
        }
        __syncthreads();
        // fc2 partial (K=64 slice)
#pragma unroll
        for (int ks = 0; ks < 4; ks++) {
            int kp = ks * 8;
            unsigned ah0, ah1, ah2, ah3, al0, al1, al2, al3;
            ldsm4(smu + K2HH, 36, m0, kp, ah0, ah1, ah2, ah3);
            ldsm4(smu + K2HL, 36, m0, kp, al0, al1, al2, al3);
#pragma unroll
            for (int tp = 0; tp < 4; tp++) {
                unsigned bh0, bh1, bh2, bh3, bl0, bl1, bl2, bl3;
                ldsm4(smu + K2W2H, 36, nh * 64 + 16 * tp, kp, bh0, bh1, bh2, bh3);
                ldsm4(smu + K2W2L, 36, nh * 64 + 16 * tp, kp, bl0, bl1, bl2, bl3);
                mma_bf16(acc2[2 * tp],     ah0, ah1, ah2, ah3, bh0, bh2);
                mma_bf16(acc2[2 * tp],     ah0, ah1, ah2, ah3, bl0, bl2);
                mma_bf16(acc2[2 * tp],     al0, al1, al2, al3, bh0, bh2);
                mma_bf16(acc2[2 * tp + 1], ah0, ah1, ah2, ah3, bh1, bh3);
                mma_bf16(acc2[2 * tp + 1], ah0, ah1, ah2, ah3, bl1, bl3);
                mma_bf16(acc2[2 * tp + 1], al0, al1, al2, al3, bh1, bh3);
            }
        }
    }
    // Y = fc2 out + bias
#pragma unroll
    for (int t = 0; t < 8; t++) {
        int col = nh * 64 + t * 8 + 2 * q;
        sm[K2Y + (m0 + g) * 133 + col]         = acc2[t][0] + b2[col];
        sm[K2Y + (m0 + g) * 133 + col + 1]     = acc2[t][1] + b2[col + 1];
        sm[K2Y + (m0 + g + 8) * 133 + col]     = acc2[t][2] + b2[col];
        sm[K2Y + (m0 + g + 8) * 133 + col + 1] = acc2[t][3] + b2[col + 1];
    }
    __syncthreads();
    // LN + residual (x1 = hi + lo)
    {
        int t = tid >> 2, ln = tid & 3;
        float* yrow = &sm[K2Y + t * 133];
        int cb = ln * 32;
        float s1 = 0.f, s2 = 0.f;
#pragma unroll 8
        for (int c = 0; c < 32; c++) {
            float v = yrow[cb + c];
            s1 += v; s2 += v * v;
        }
        s1 += __shfl_xor_sync(0xffffffffu, s1, 1);
        s2 += __shfl_xor_sync(0xffffffffu, s2, 1);
        s1 += __shfl_xor_sync(0xffffffffu, s1, 2);
        s2 += __shfl_xor_sync(0xffffffffu, s2, 2);
        float mu = s1 * (1.0f / 128.0f);
        float var = fmaxf(s2 * (1.0f / 128.0f) - mu * mu, 0.0f);
        float rs = rsqrtf(var + 1e-5f);
#pragma unroll 8
        for (int cp = 0; cp < 16; cp++) {
            unsigned uh = smu[K2XHI + t * 68 + (cb >> 1) + cp];
            unsigned ul = smu[K2XLO + t * 68 + (cb >> 1) + cp];
            float2 fh = unpack2(uh), fl = unpack2(ul);
            int cc = cb + 2 * cp;
            float l0 = (yrow[cc] - mu) * rs * n2w[cc] + n2b[cc];
            float l1 = (yrow[cc + 1] - mu) * rs * n2w[cc + 1] + n2b[cc + 1];
            yrow[cc]     = fh.x + fl.x + l0;
            yrow[cc + 1] = fh.y + fl.y + l1;
        }
    }
    __syncthreads();
    // transposed store -> NCHW
    {
        float* ob = out + (size_t)b * 128 * HW + h * 128 + w0;
#pragma unroll
        for (int it = 0; it < 32; it++) {
            int idx = it * 256 + tid;
            int c = idx >> 6, ww = idx & 63;
            ob[(size_t)c * HW + ww] = sm[K2Y + ww * 133 + c];
        }
    }
}

// ------------------------------ launch --------------------------------------
extern "C" void kernel_launch(void* const* d_in, const int* in_sizes, int n_in,
                              void* d_out, int out_size) {
    const float* x    = (const float*)d_in[0];
    const float* n1w  = (const float*)d_in[1];
    const float* n1b  = (const float*)d_in[2];
    const float* qkvw = (const float*)d_in[3];
    const float* qb   = (const float*)d_in[4];
    const float* vb   = (const float*)d_in[5];
    const float* ls   = (const float*)d_in[6];
    const float* cw1  = (const float*)d_in[7];
    const float* cb1  = (const float*)d_in[8];
    const float* cw2  = (const float*)d_in[9];
    const float* pw   = (const float*)d_in[10];
    const float* pb   = (const float*)d_in[11];
    const float* n2w  = (const float*)d_in[12];
    const float* n2b  = (const float*)d_in[13];
    const float* f1w  = (const float*)d_in[14];
    const float* f1b  = (const float*)d_in[15];
    const float* f2w  = (const float*)d_in[16];
    const float* f2b  = (const float*)d_in[17];
    float* out = (float*)d_out;

    cudaFuncSetAttribute(k1_attn, cudaFuncAttributeMaxDynamicSharedMemorySize, K1_SMEM);
    cudaFuncSetAttribute(k2_mlp,  cudaFuncAttributeMaxDynamicSharedMemorySize, K2_SMEM);

    k0_bias<<<1, 256>>>(cw1, cb1, cw2);
    k0_wsplit<<<384, 256>>>(qkvw, pw, f1w, f2w);
    k1_attn<<<4096, 256, K1_SMEM>>>(x, n1w, n1b, qb, vb, ls, pb);
    k2_mlp<<<4096, 256, K2_SMEM>>>(n2w, n2b, f1b, f2b, out);
}

// round 8
// speedup vs baseline: 2.6645x; 1.1244x over previous
#include <cuda_runtime.h>
#include <cuda_bf16.h>
#include <math.h>

#define HW 16384
#define LOG100f 4.605170185988092f

__device__ float g_x1[16u * HW * 128u];   // x1 token-major [tok][128]
__device__ float g_bias16[4 * 64 * 64];   // 16*sigmoid(cpb bias)
// pre-split weights, bf16 pairs packed in u32 along K
__device__ unsigned g_qkvh[24576], g_qkvl[24576];   // [384][64]
__device__ unsigned g_pwh[8192],   g_pwl[8192];     // [128][64]
__device__ unsigned g_f1h[32768],  g_f1l[32768];    // [512][64]
__device__ unsigned g_f2h[32768],  g_f2l[32768];    // [128][256]

// ---------------------------------------------------------------------------
__device__ __forceinline__ void mma_bf16(float d[4], unsigned a0, unsigned a1,
                                         unsigned a2, unsigned a3,
                                         unsigned b0, unsigned b1) {
    asm volatile(
        "mma.sync.aligned.m16n8k16.row.col.f32.bf16.bf16.f32 "
        "{%0,%1,%2,%3},{%4,%5,%6,%7},{%8,%9},{%0,%1,%2,%3};"
        : "+f"(d[0]), "+f"(d[1]), "+f"(d[2]), "+f"(d[3])
        : "r"(a0), "r"(a1), "r"(a2), "r"(a3), "r"(b0), "r"(b1));
}

// ldmatrix x4: 16 rows r0.., pair cols kp..kp+3 / kp+4..kp+7
__device__ __forceinline__ void ldsm4(const unsigned* base, int P, int r0, int kp,
                                      unsigned& o0, unsigned& o1, unsigned& o2, unsigned& o3) {
    int lane = threadIdx.x & 31;
    const unsigned* p = base + (r0 + (lane & 15)) * P + kp + ((lane >> 4) << 2);
    unsigned a = (unsigned)__cvta_generic_to_shared(p);
    asm volatile("ldmatrix.sync.aligned.m8n8.x4.shared.b16 {%0,%1,%2,%3}, [%4];"
                 : "=r"(o0), "=r"(o1), "=r"(o2), "=r"(o3) : "r"(a));
}

// ldmatrix x2: one n8k16 B fragment (rows r0..r0+7)
__device__ __forceinline__ void ldsm2(const unsigned* base, int P, int r0, int kp,
                                      unsigned& o0, unsigned& o1) {
    int lane = threadIdx.x & 31;
    const unsigned* p = base + (r0 + (lane & 7)) * P + kp + (((lane >> 3) & 1) << 2);
    unsigned a = (unsigned)__cvta_generic_to_shared(p);
    asm volatile("ldmatrix.sync.aligned.m8n8.x2.shared.b16 {%0,%1}, [%2];"
                 : "=r"(o0), "=r"(o1) : "r"(a));
}

__device__ __forceinline__ void split2(float v0, float v1, unsigned& hi, unsigned& lo) {
    __nv_bfloat16 h0 = __float2bfloat16(v0);
    __nv_bfloat16 h1 = __float2bfloat16(v1);
    float r0 = v0 - __bfloat162float(h0);
    float r1 = v1 - __bfloat162float(h1);
    __nv_bfloat16 l0 = __float2bfloat16(r0);
    __nv_bfloat16 l1 = __float2bfloat16(r1);
    hi = (unsigned)__bfloat16_as_ushort(h0) | ((unsigned)__bfloat16_as_ushort(h1) << 16);
    lo = (unsigned)__bfloat16_as_ushort(l0) | ((unsigned)__bfloat16_as_ushort(l1) << 16);
}

__device__ __forceinline__ float2 unpack2(unsigned u) {
    __nv_bfloat162 b = *reinterpret_cast<__nv_bfloat162*>(&u);
    return __bfloat1622float2(b);
}

// ------------------------------ K0 ------------------------------------------
__global__ void k0_bias(const float* __restrict__ w1, const float* __restrict__ b1,
                        const float* __restrict__ w2) {
    __shared__ float tab[225][4];
    int tid = threadIdx.x;
    if (tid < 225) {
        int a = tid / 15, bb = tid % 15;
        float v0 = (a - 7) * (8.0f / 7.0f), v1 = (bb - 7) * (8.0f / 7.0f);
        float g0 = copysignf(log2f(fabsf(v0) + 1.0f) * (1.0f / 3.0f), v0);
        float g1 = copysignf(log2f(fabsf(v1) + 1.0f) * (1.0f / 3.0f), v1);
        float o0 = 0, o1 = 0, o2 = 0, o3 = 0;
        for (int j = 0; j < 512; j++) {
            float hv = fmaxf(w1[2 * j] * g0 + w1[2 * j + 1] * g1 + b1[j], 0.0f);
            o0 += hv * w2[j];        o1 += hv * w2[512 + j];
            o2 += hv * w2[1024 + j]; o3 += hv * w2[1536 + j];
        }
        tab[tid][0] = o0; tab[tid][1] = o1; tab[tid][2] = o2; tab[tid][3] = o3;
    }
    __syncthreads();
    for (int e = tid; e < 4 * 64 * 64; e += blockDim.x) {
        int h = e >> 12, i = (e >> 6) & 63, j = e & 63;
        int dy = (i >> 3) - (j >> 3) + 7, dx = (i & 7) - (j & 7) + 7;
        float v = tab[dy * 15 + dx][h];
        g_bias16[e] = 16.0f / (1.0f + expf(-v));
    }
}

__device__ __forceinline__ void splitpair(const float* w, unsigned* hi, unsigned* lo, int i) {
    split2(w[2 * i], w[2 * i + 1], hi[i], lo[i]);
}

__global__ void k0_wsplit(const float* __restrict__ qkvw, const float* __restrict__ pw,
                          const float* __restrict__ f1w, const float* __restrict__ f2w) {
    int i = blockIdx.x * 256 + threadIdx.x;
    if (i < 24576)       splitpair(qkvw, g_qkvh, g_qkvl, i);
    else if (i < 32768)  splitpair(pw,  g_pwh,  g_pwl,  i - 24576);
    else if (i < 65536)  splitpair(f1w, g_f1h,  g_f1l,  i - 32768);
    else if (i < 98304)  splitpair(f2w, g_f2h,  g_f2l,  i - 65536);
}

// ------------------------------ K1: attention -------------------------------
#define XHI  0        // [64][68] u32
#define XLO  4352
#define QKVO 8704     // [384][68] f32 ; reused: Pout rows [64][132]
#define WHI  34816    // [64][68] u32 weight stage hi
#define WLO  39168    // [64][68] u32 weight stage lo
#define QHI  34816    // [64][20]
#define QLO  36096
#define KHI  37376
#define KLO  38656
#define ATTN 39936    // [64][68] f32
#define PHI  34816    // [64][36]
#define PLO  37120
#define VHI  39936    // [32][36]
#define VLO  41088
#define OHI  44288    // [64][68] u32
#define OLO  48640
#define IQ   52992
#define IK   53056
#define RG   53120
#define K1_SMEM (53184 * 4)

__global__ void __launch_bounds__(512, 1)
k1_attn(const float* __restrict__ x,
        const float* __restrict__ n1w, const float* __restrict__ n1b,
        const float* __restrict__ qb, const float* __restrict__ vb,
        const float* __restrict__ ls, const float* __restrict__ pb) {
    extern __shared__ float sm[];
    unsigned* smu = (unsigned*)sm;
    int tid = threadIdx.x;
    int wid = tid >> 5, lane = tid & 31;
    int g = lane >> 2, q = lane & 3;
    int b = blockIdx.x >> 8, widx = blockIdx.x & 255;
    int wy = widx >> 4, wx = widx & 15;

    // phase 0: gather shifted window, split to bf16 pairs [t][cpair]
    {
        const float* xb = x + (size_t)b * 128 * HW;
#pragma unroll
        for (int it = 0; it < 8; it++) {              // 8*512 = 4096 = 64 t * 64 cp
            int idx = it * 512 + tid;
            int t = idx & 63, cp = idx >> 6;
            int ti = t >> 3, tj = t & 7;
            int hh = (wy * 8 + ti + 4) & 127;
            int ww = (wx * 8 + tj + 4) & 127;
            const float* p = xb + (size_t)(2 * cp) * HW + hh * 128 + ww;
            float v0 = p[0], v1 = p[HW];
            split2(v0, v1, smu[XHI + t * 68 + cp], smu[XLO + t * 68 + cp]);
        }
        if (tid < 64) {
            int ti = tid >> 3, tj = tid & 7;
            int hs = wy * 8 + ti, ws = wx * 8 + tj;
            int hr = hs < 120 ? 0 : (hs < 124 ? 1 : 2);
            int wr = ws < 120 ? 0 : (ws < 124 ? 1 : 2);
            sm[RG + tid] = (float)(hr * 3 + wr);
        }
    }

    int mi = wid & 3, nh = wid >> 2;   // 4 x 4 warp grid
    int m0 = mi * 16;
    int n0 = nh * 16;

    // phase 1: QKV GEMM, 6 chunks of 64 cols, warp tile m16 x n16
    for (int ch = 0; ch < 6; ch++) {
        __syncthreads();
#pragma unroll
        for (int it = 0; it < 8; it++) {
            int p = it * 512 + tid;
            int r = p >> 6, c = p & 63;
            smu[WHI + r * 68 + c] = g_qkvh[(ch * 64 + r) * 64 + c];
            smu[WLO + r * 68 + c] = g_qkvl[(ch * 64 + r) * 64 + c];
        }
        __syncthreads();
        float acc[2][4] = {};
#pragma unroll
        for (int ks = 0; ks < 8; ks++) {
            int kp = ks * 8;
            unsigned ah0, ah1, ah2, ah3, al0, al1, al2, al3;
            ldsm4(smu + XHI, 68, m0, kp, ah0, ah1, ah2, ah3);
            ldsm4(smu + XLO, 68, m0, kp, al0, al1, al2, al3);
            unsigned bh0, bh1, bh2, bh3, bl0, bl1, bl2, bl3;
            ldsm4(smu + WHI, 68, n0, kp, bh0, bh1, bh2, bh3);
            ldsm4(smu + WLO, 68, n0, kp, bl0, bl1, bl2, bl3);
            mma_bf16(acc[0], ah0, ah1, ah2, ah3, bh0, bh2);
            mma_bf16(acc[0], ah0, ah1, ah2, ah3, bl0, bl2);
            mma_bf16(acc[0], al0, al1, al2, al3, bh0, bh2);
            mma_bf16(acc[1], ah0, ah1, ah2, ah3, bh1, bh3);
            mma_bf16(acc[1], ah0, ah1, ah2, ah3, bl1, bl3);
            mma_bf16(acc[1], al0, al1, al2, al3, bh1, bh3);
        }
#pragma unroll
        for (int nt = 0; nt < 2; nt++) {
            int col0 = ch * 64 + n0 + nt * 8 + 2 * q;
            float b0c = col0 < 128 ? qb[col0] : (col0 >= 256 ? vb[col0 - 256] : 0.0f);
            float b1c = col0 + 1 < 128 ? qb[col0 + 1] : (col0 + 1 >= 256 ? vb[col0 - 255] : 0.0f);
            sm[QKVO + col0 * 68 + m0 + g]           = acc[nt][0] + b0c;
            sm[QKVO + (col0 + 1) * 68 + m0 + g]     = acc[nt][1] + b1c;
            sm[QKVO + col0 * 68 + m0 + g + 8]       = acc[nt][2] + b0c;
            sm[QKVO + (col0 + 1) * 68 + m0 + g + 8] = acc[nt][3] + b1c;
        }
    }

    // phase 2: attention per head
    for (int h = 0; h < 4; h++) {
        __syncthreads();
        // inverse norms: 4 threads per row, 128 rows (q then k)
        {
            int r = tid >> 2, quar = tid & 3;
            int t = r & 63;
            int cbase = (r < 64 ? 0 : 128) + h * 32 + quar * 8;
            float s = 0.f;
#pragma unroll
            for (int d = 0; d < 8; d++) {
                float v = sm[QKVO + (cbase + d) * 68 + t];
                s += v * v;
            }
            s += __shfl_xor_sync(0xffffffffu, s, 1);
            s += __shfl_xor_sync(0xffffffffu, s, 2);
            if (quar == 0)
                sm[(r < 64 ? IQ : IK) + t] = 1.0f / fmaxf(sqrtf(s), 1e-12f);
        }
        __syncthreads();
        // normalize + split Q,K -> [t][dpair] pitch 20 (norms folded in)
#pragma unroll
        for (int it = 0; it < 4; it++) {              // 4*512 = 2048 = 2*64*16
            int idx = it * 512 + tid;
            int t = idx & 63, p = (idx >> 6) & 15, m = idx >> 10;
            int cbase = (m ? 128 : 0) + h * 32 + 2 * p;
            float inv = sm[(m ? IK : IQ) + t];
            float v0 = sm[QKVO + cbase * 68 + t] * inv;
            float v1 = sm[QKVO + (cbase + 1) * 68 + t] * inv;
            split2(v0, v1, smu[(m ? KHI : QHI) + t * 20 + p],
                   smu[(m ? KLO : QLO) + t * 20 + p]);
        }
        __syncthreads();
        // logits MMA: warp tile m16 x n16
        {
            float scale = __expf(fminf(ls[h], LOG100f));
            float acc[2][4] = {};
#pragma unroll
            for (int ks = 0; ks < 2; ks++) {
                int kp = ks * 8;
                unsigned ah0, ah1, ah2, ah3, al0, al1, al2, al3;
                ldsm4(smu + QHI, 20, m0, kp, ah0, ah1, ah2, ah3);
                ldsm4(smu + QLO, 20, m0, kp, al0, al1, al2, al3);
                unsigned bh0, bh1, bh2, bh3, bl0, bl1, bl2, bl3;
                ldsm4(smu + KHI, 20, n0, kp, bh0, bh1, bh2, bh3);
                ldsm4(smu + KLO, 20, n0, kp, bl0, bl1, bl2, bl3);
                mma_bf16(acc[0], ah0, ah1, ah2, ah3, bh0, bh2);
                mma_bf16(acc[0], ah0, ah1, ah2, ah3, bl0, bl2);
                mma_bf16(acc[0], al0, al1, al2, al3, bh0, bh2);
                mma_bf16(acc[1], ah0, ah1, ah2, ah3, bh1, bh3);
                mma_bf16(acc[1], ah0, ah1, ah2, ah3, bl1, bl3);
                mma_bf16(acc[1], al0, al1, al2, al3, bh1, bh3);
            }
            int row0 = m0 + g, row1 = row0 + 8;
            float rt0 = sm[RG + row0], rt1 = sm[RG + row1];
#pragma unroll
            for (int nt = 0; nt < 2; nt++) {
                int col = n0 + nt * 8 + 2 * q;
                float ru0 = sm[RG + col], ru1 = sm[RG + col + 1];
                float2 b0v = *(const float2*)&g_bias16[(h * 64 + row0) * 64 + col];
                float2 b1v = *(const float2*)&g_bias16[(h * 64 + row1) * 64 + col];
                sm[ATTN + row0 * 68 + col]     = acc[nt][0] * scale + b0v.x + (rt0 != ru0 ? -100.f : 0.f);
                sm[ATTN + row0 * 68 + col + 1] = acc[nt][1] * scale + b0v.y + (rt0 != ru1 ? -100.f : 0.f);
                sm[ATTN + row1 * 68 + col]     = acc[nt][2] * scale + b1v.x + (rt1 != ru0 ? -100.f : 0.f);
                sm[ATTN + row1 * 68 + col + 1] = acc[nt][3] * scale + b1v.y + (rt1 != ru1 ? -100.f : 0.f);
            }
        }
        __syncthreads();
        // softmax (8 threads/row) -> P split [t][upair] pitch 36
        {
            int t = tid >> 3, ln = tid & 7;
            const float* row = &sm[ATTN + t * 68 + ln * 8];
            float e[8];
            float mx = -1e30f;
#pragma unroll
            for (int i = 0; i < 8; i++) { e[i] = row[i]; mx = fmaxf(mx, e[i]); }
            mx = fmaxf(mx, __shfl_xor_sync(0xffffffffu, mx, 1));
            mx = fmaxf(mx, __shfl_xor_sync(0xffffffffu, mx, 2));
            mx = fmaxf(mx, __shfl_xor_sync(0xffffffffu, mx, 4));
            float s = 0.f;
#pragma unroll
            for (int i = 0; i < 8; i++) { e[i] = __expf(e[i] - mx); s += e[i]; }
            s += __shfl_xor_sync(0xffffffffu, s, 1);
            s += __shfl_xor_sync(0xffffffffu, s, 2);
            s += __shfl_xor_sync(0xffffffffu, s, 4);
            float inv = 1.0f / s;
#pragma unroll
            for (int i = 0; i < 4; i++)
                split2(e[2 * i] * inv, e[2 * i + 1] * inv,
                       smu[PHI + t * 36 + ln * 4 + i], smu[PLO + t * 36 + ln * 4 + i]);
        }
        __syncthreads();
        // V split -> [d][upair] pitch 36
#pragma unroll
        for (int it = 0; it < 2; it++) {              // 2*512 = 1024 = 32 d * 32 up
            int idx = it * 512 + tid;
            int u = idx & 31, d = idx >> 5;
            float2 v = *(const float2*)&sm[QKVO + (256 + h * 32 + d) * 68 + 2 * u];
            split2(v.x, v.y, smu[VHI + d * 36 + u], smu[VLO + d * 36 + u]);
        }
        __syncthreads();
        // PV MMA: out [64 t][32 d], warp tile m16 x n8 (16 warps: 4 mi x 4 nf)
        {
            int n0v = nh * 8;
            float acc[4] = {};
#pragma unroll
            for (int ks = 0; ks < 4; ks++) {
                int kp = ks * 8;
                unsigned ah0, ah1, ah2, ah3, al0, al1, al2, al3;
                ldsm4(smu + PHI, 36, m0, kp, ah0, ah1, ah2, ah3);
                ldsm4(smu + PLO, 36, m0, kp, al0, al1, al2, al3);
                unsigned bh0, bh1, bl0, bl1;
                ldsm2(smu + VHI, 36, n0v, kp, bh0, bh1);
                ldsm2(smu + VLO, 36, n0v, kp, bl0, bl1);
                mma_bf16(acc, ah0, ah1, ah2, ah3, bh0, bh1);
                mma_bf16(acc, ah0, ah1, ah2, ah3, bl0, bl1);
                mma_bf16(acc, al0, al1, al2, al3, bh0, bh1);
            }
            int pr = h * 16 + (n0v >> 1) + q;
            split2(acc[0], acc[1], smu[OHI + (m0 + g) * 68 + pr], smu[OLO + (m0 + g) * 68 + pr]);
            split2(acc[2], acc[3], smu[OHI + (m0 + g + 8) * 68 + pr], smu[OLO + (m0 + g + 8) * 68 + pr]);
        }
    }

    // phase 3: proj GEMM, 2 chunks of 64 cols, warp m16 x n16 -> Pout rows [t][132]
    for (int ch = 0; ch < 2; ch++) {
        __syncthreads();
#pragma unroll
        for (int it = 0; it < 8; it++) {
            int p = it * 512 + tid;
            int r = p >> 6, c = p & 63;
            smu[WHI + r * 68 + c] = g_pwh[(ch * 64 + r) * 64 + c];
            smu[WLO + r * 68 + c] = g_pwl[(ch * 64 + r) * 64 + c];
        }
        __syncthreads();
        float acc[2][4] = {};
#pragma unroll
        for (int ks = 0; ks < 8; ks++) {
            int kp = ks * 8;
            unsigned ah0, ah1, ah2, ah3, al0, al1, al2, al3;
            ldsm4(smu + OHI, 68, m0, kp, ah0, ah1, ah2, ah3);
            ldsm4(smu + OLO, 68, m0, kp, al0, al1, al2, al3);
            unsigned bh0, bh1, bh2, bh3, bl0, bl1, bl2, bl3;
            ldsm4(smu + WHI, 68, n0, kp, bh0, bh1, bh2, bh3);
            ldsm4(smu + WLO, 68, n0, kp, bl0, bl1, bl2, bl3);
            mma_bf16(acc[0], ah0, ah1, ah2, ah3, bh0, bh2);
            mma_bf16(acc[0], ah0, ah1, ah2, ah3, bl0, bl2);
            mma_bf16(acc[0], al0, al1, al2, al3, bh0, bh2);
            mma_bf16(acc[1], ah0, ah1, ah2, ah3, bh1, bh3);
            mma_bf16(acc[1], ah0, ah1, ah2, ah3, bl1, bl3);
            mma_bf16(acc[1], al0, al1, al2, al3, bh1, bh3);
        }
#pragma unroll
        for (int nt = 0; nt < 2; nt++) {
            int col0 = ch * 64 + n0 + nt * 8 + 2 * q;
            sm[QKVO + (m0 + g) * 132 + col0]         = acc[nt][0] + pb[col0];
            sm[QKVO + (m0 + g) * 132 + col0 + 1]     = acc[nt][1] + pb[col0 + 1];
            sm[QKVO + (m0 + g + 8) * 132 + col0]     = acc[nt][2] + pb[col0];
            sm[QKVO + (m0 + g + 8) * 132 + col0 + 1] = acc[nt][3] + pb[col0 + 1];
        }
    }

    // phase 4: LN + residual -> g_x1 (8 threads/row)
    __syncthreads();
    {
        int t = tid >> 3, ln = tid & 7;
        const float* prow = &sm[QKVO + t * 132];
        int cb = ln * 16;
        float s1 = 0.f, s2 = 0.f;
#pragma unroll
        for (int c = 0; c < 16; c++) {
            float v = prow[cb + c];
            s1 += v; s2 += v * v;
        }
        s1 += __shfl_xor_sync(0xffffffffu, s1, 1);
        s2 += __shfl_xor_sync(0xffffffffu, s2, 1);
        s1 += __shfl_xor_sync(0xffffffffu, s1, 2);
        s2 += __shfl_xor_sync(0xffffffffu, s2, 2);
        s1 += __shfl_xor_sync(0xffffffffu, s1, 4);
        s2 += __shfl_xor_sync(0xffffffffu, s2, 4);
        float mu = s1 * (1.0f / 128.0f);
        float var = fmaxf(s2 * (1.0f / 128.0f) - mu * mu, 0.0f);
        float rs = rsqrtf(var + 1e-5f);
        int ti = t >> 3, tj = t & 7;
        int hh = (wy * 8 + ti + 4) & 127;
        int ww = (wx * 8 + tj + 4) & 127;
        float* dst = &g_x1[((size_t)b * HW + hh * 128 + ww) * 128];
#pragma unroll
        for (int cp = 0; cp < 8; cp++) {
            unsigned uh = smu[XHI + t * 68 + ln * 8 + cp];
            unsigned ul = smu[XLO + t * 68 + ln * 8 + cp];
            float2 fh = unpack2(uh), fl = unpack2(ul);
            int cc = cb + 2 * cp;
            float l0 = (prow[cc] - mu) * rs * n1w[cc] + n1b[cc];
            float l1 = (prow[cc + 1] - mu) * rs * n1w[cc + 1] + n1b[cc + 1];
            dst[cc]     = fh.x + fl.x + l0;
            dst[cc + 1] = fh.y + fl.y + l1;
        }
    }
}

// ------------------------------ K2: MLP (128 tokens/CTA) --------------------
#define K2XHI 0       // [128][68]
#define K2XLO 8704
#define K2W1H 17408   // [64][68]
#define K2W1L 21760
#define K2HH  26112   // [128][36]
#define K2HL  30720
#define K2W2H 35328   // [128][36]
#define K2W2L 39936   // ends 44544
#define K2Y   26112   // [128][133] aliased over H+W2 (dead after loop)
#define K2_SMEM (44544 * 4)

__global__ void __launch_bounds__(512, 1)
k2_mlp(const float* __restrict__ n2w, const float* __restrict__ n2b,
       const float* __restrict__ b1, const float* __restrict__ b2,
       float* __restrict__ out) {
    extern __shared__ float sm[];
    unsigned* smu = (unsigned*)sm;
    int tid = threadIdx.x;
    int wid = tid >> 5, lane = tid & 31;
    int g = lane >> 2, q = lane & 3;
    int p0 = blockIdx.x * 128;
    int b = p0 >> 14, h = (p0 >> 7) & 127;

    // load + split x1 (128 tokens)
#pragma unroll
    for (int it = 0; it < 16; it++) {                 // 16*512 = 8192 = 128 t * 64 cp
        int idx = it * 512 + tid;
        int cp = idx & 63, t = idx >> 6;
        float2 v = *(const float2*)&g_x1[((size_t)p0 + t) * 128 + 2 * cp];
        split2(v.x, v.y, smu[K2XHI + t * 68 + cp], smu[K2XLO + t * 68 + cp]);
    }

    int mi = wid & 7, nh = wid >> 3;   // 8 x 2 warp grid
    int m0 = mi * 16;
    int n0w = nh * 32;
    float acc2[8][4];
#pragma unroll
    for (int t = 0; t < 8; t++)
#pragma unroll
        for (int j = 0; j < 4; j++) acc2[t][j] = 0.f;

    for (int ch = 0; ch < 8; ch++) {
        __syncthreads();
#pragma unroll
        for (int it = 0; it < 8; it++) {   // stage fc1 chunk [64][64]
            int p = it * 512 + tid;
            int r = p >> 6, c = p & 63;
            smu[K2W1H + r * 68 + c] = g_f1h[(ch * 64 + r) * 64 + c];
            smu[K2W1L + r * 68 + c] = g_f1l[(ch * 64 + r) * 64 + c];
        }
#pragma unroll
        for (int it = 0; it < 8; it++) {   // stage fc2 k-slice [128][32]
            int p = it * 512 + tid;
            int r = p >> 5, c = p & 31;
            smu[K2W2H + r * 36 + c] = g_f2h[r * 256 + ch * 32 + c];
            smu[K2W2L + r * 36 + c] = g_f2l[r * 256 + ch * 32 + c];
        }
        __syncthreads();
        // fc1 chunk: warp m16 x n32
        float acc[4][4] = {};
#pragma unroll
        for (int ks = 0; ks < 8; ks++) {
            int kp = ks * 8;
            unsigned ah0, ah1, ah2, ah3, al0, al1, al2, al3;
            ldsm4(smu + K2XHI, 68, m0, kp, ah0, ah1, ah2, ah3);
            ldsm4(smu + K2XLO, 68, m0, kp, al0, al1, al2, al3);
#pragma unroll
            for (int hf = 0; hf < 2; hf++) {
                unsigned bh0, bh1, bh2, bh3, bl0, bl1, bl2, bl3;
                ldsm4(smu + K2W1H, 68, n0w + 16 * hf, kp, bh0, bh1, bh2, bh3);
                ldsm4(smu + K2W1L, 68, n0w + 16 * hf, kp, bl0, bl1, bl2, bl3);
                mma_bf16(acc[2 * hf],     ah0, ah1, ah2, ah3, bh0, bh2);
                mma_bf16(acc[2 * hf],     ah0, ah1, ah2, ah3, bl0, bl2);
                mma_bf16(acc[2 * hf],     al0, al1, al2, al3, bh0, bh2);
                mma_bf16(acc[2 * hf + 1], ah0, ah1, ah2, ah3, bh1, bh3);
                mma_bf16(acc[2 * hf + 1], ah0, ah1, ah2, ah3, bl1, bl3);
                mma_bf16(acc[2 * hf + 1], al0, al1, al2, al3, bh1, bh3);
            }
        }
        // silu + split -> H [t][hpair] pitch 36
#pragma unroll
        for (int nt = 0; nt < 4; nt++) {
            int c0 = n0w + nt * 8 + 2 * q;
            int col = ch * 64 + c0;
            float v0 = acc[nt][0] + b1[col],     v1 = acc[nt][1] + b1[col + 1];
            float v2 = acc[nt][2] + b1[col],     v3 = acc[nt][3] + b1[col + 1];
            v0 = v0 / (1.0f + __expf(-v0));
            v1 = v1 / (1.0f + __expf(-v1));
            v2 = v2 / (1.0f + __expf(-v2));
            v3 = v3 / (1.0f + __expf(-v3));
            int pp = (c0 >> 1);
            split2(v0, v1, smu[K2HH + (m0 + g) * 36 + pp], smu[K2HL + (m0 + g) * 36 + pp]);
            split2(v2, v3, smu[K2HH + (m0 + g + 8) * 36 + pp], smu[K2HL + (m0 + g + 8) * 36 + pp]);
        }
        __syncthreads();
        // fc2 partial: warp m16 x n64
#pragma unroll
        for (int ks = 0; ks < 4; ks++) {
            int kp = ks * 8;
            unsigned ah0, ah1, ah2, ah3, al0, al1, al2, al3;
            ldsm4(smu + K2HH, 36, m0, kp, ah0, ah1, ah2, ah3);
            ldsm4(smu + K2HL, 36, m0, kp, al0, al1, al2, al3);
#pragma unroll
            for (int tp = 0; tp < 4; tp++) {
                unsigned bh0, bh1, bh2, bh3, bl0, bl1, bl2, bl3;
                ldsm4(smu + K2W2H, 36, nh * 64 + 16 * tp, kp, bh0, bh1, bh2, bh3);
                ldsm4(smu + K2W2L, 36, nh * 64 + 16 * tp, kp, bl0, bl1, bl2, bl3);
                mma_bf16(acc2[2 * tp],     ah0, ah1, ah2, ah3, bh0, bh2);
                mma_bf16(acc2[2 * tp],     ah0, ah1, ah2, ah3, bl0, bl2);
                mma_bf16(acc2[2 * tp],     al0, al1, al2, al3, bh0, bh2);
                mma_bf16(acc2[2 * tp + 1], ah0, ah1, ah2, ah3, bh1, bh3);
                mma_bf16(acc2[2 * tp + 1], ah0, ah1, ah2, ah3, bl1, bl3);
                mma_bf16(acc2[2 * tp + 1], al0, al1, al2, al3, bh1, bh3);
            }
        }
    }
    __syncthreads();   // H/W2 dead; Y aliases them
    // Y = fc2 out + bias
#pragma unroll
    for (int t = 0; t < 8; t++) {
        int col = nh * 64 + t * 8 + 2 * q;
        sm[K2Y + (m0 + g) * 133 + col]         = acc2[t][0] + b2[col];
        sm[K2Y + (m0 + g) * 133 + col + 1]     = acc2[t][1] + b2[col + 1];
        sm[K2Y + (m0 + g + 8) * 133 + col]     = acc2[t][2] + b2[col];
        sm[K2Y + (m0 + g + 8) * 133 + col + 1] = acc2[t][3] + b2[col + 1];
    }
    __syncthreads();
    // LN + residual (x1 = hi + lo), 4 threads/row
    {
        int t = tid >> 2, ln = tid & 3;
        float* yrow = &sm[K2Y + t * 133];
        int cb = ln * 32;
        float s1 = 0.f, s2 = 0.f;
#pragma unroll 8
        for (int c = 0; c < 32; c++) {
            float v = yrow[cb + c];
            s1 += v; s2 += v * v;
        }
        s1 += __shfl_xor_sync(0xffffffffu, s1, 1);
        s2 += __shfl_xor_sync(0xffffffffu, s2, 1);
        s1 += __shfl_xor_sync(0xffffffffu, s1, 2);
        s2 += __shfl_xor_sync(0xffffffffu, s2, 2);
        float mu = s1 * (1.0f / 128.0f);
        float var = fmaxf(s2 * (1.0f / 128.0f) - mu * mu, 0.0f);
        float rs = rsqrtf(var + 1e-5f);
#pragma unroll 8
        for (int cp = 0; cp < 16; cp++) {
            unsigned uh = smu[K2XHI + t * 68 + (cb >> 1) + cp];
            unsigned ul = smu[K2XLO + t * 68 + (cb >> 1) + cp];
            float2 fh = unpack2(uh), fl = unpack2(ul);
            int cc = cb + 2 * cp;
            float l0 = (yrow[cc] - mu) * rs * n2w[cc] + n2b[cc];
            float l1 = (yrow[cc + 1] - mu) * rs * n2w[cc + 1] + n2b[cc + 1];
            yrow[cc]     = fh.x + fl.x + l0;
            yrow[cc + 1] = fh.y + fl.y + l1;
        }
    }
    __syncthreads();
    // transposed store -> NCHW (128 tokens = full image row h)
    {
        float* ob = out + (size_t)b * 128 * HW + h * 128;
#pragma unroll
        for (int it = 0; it < 32; it++) {
            int idx = it * 512 + tid;
            int c = idx >> 7, w = idx & 127;
            ob[(size_t)c * HW + w] = sm[K2Y + w * 133 + c];
        }
    }
}

// ------------------------------ launch --------------------------------------
extern "C" void kernel_launch(void* const* d_in, const int* in_sizes, int n_in,
                              void* d_out, int out_size) {
    const float* x    = (const float*)d_in[0];
    const float* n1w  = (const float*)d_in[1];
    const float* n1b  = (const float*)d_in[2];
    const float* qkvw = (const float*)d_in[3];
    const float* qb   = (const float*)d_in[4];
    const float* vb   = (const float*)d_in[5];
    const float* ls   = (const float*)d_in[6];
    const float* cw1  = (const float*)d_in[7];
    const float* cb1  = (const float*)d_in[8];
    const float* cw2  = (const float*)d_in[9];
    const float* pw   = (const float*)d_in[10];
    const float* pb   = (const float*)d_in[11];
    const float* n2w  = (const float*)d_in[12];
    const float* n2b  = (const float*)d_in[13];
    const float* f1w  = (const float*)d_in[14];
    const float* f1b  = (const float*)d_in[15];
    const float* f2w  = (const float*)d_in[16];
    const float* f2b  = (const float*)d_in[17];
    float* out = (float*)d_out;

    cudaFuncSetAttribute(k1_attn, cudaFuncAttributeMaxDynamicSharedMemorySize, K1_SMEM);
    cudaFuncSetAttribute(k2_mlp,  cudaFuncAttributeMaxDynamicSharedMemorySize, K2_SMEM);

    k0_bias<<<1, 256>>>(cw1, cb1, cw2);
    k0_wsplit<<<384, 256>>>(qkvw, pw, f1w, f2w);
    k1_attn<<<4096, 512, K1_SMEM>>>(x, n1w, n1b, qb, vb, ls, pb);
    k2_mlp<<<2048, 512, K2_SMEM>>>(n2w, n2b, f1b, f2b, out);
}

// round 9
// speedup vs baseline: 2.8584x; 1.0728x over previous
#include <cuda_runtime.h>
#include <cuda_bf16.h>
#include <math.h>

#define HW 16384
#define LOG100f 4.605170185988092f

__device__ float g_x1[16u * HW * 128u];   // x1 token-major [tok][128]
__device__ float g_bias16[4 * 64 * 64];   // 16*sigmoid(cpb bias)
// pre-split weights, bf16 pairs packed in u32 along K
__device__ unsigned g_qkvh[24576], g_qkvl[24576];   // [384][64]
__device__ unsigned g_pwh[8192],   g_pwl[8192];     // [128][64]
__device__ unsigned g_f1h[32768],  g_f1l[32768];    // [512][64]
__device__ unsigned g_f2h[32768],  g_f2l[32768];    // [128][256]

// ---------------------------------------------------------------------------
__device__ __forceinline__ void mma_bf16(float d[4], unsigned a0, unsigned a1,
                                         unsigned a2, unsigned a3,
                                         unsigned b0, unsigned b1) {
    asm volatile(
        "mma.sync.aligned.m16n8k16.row.col.f32.bf16.bf16.f32 "
        "{%0,%1,%2,%3},{%4,%5,%6,%7},{%8,%9},{%0,%1,%2,%3};"
        : "+f"(d[0]), "+f"(d[1]), "+f"(d[2]), "+f"(d[3])
        : "r"(a0), "r"(a1), "r"(a2), "r"(a3), "r"(b0), "r"(b1));
}

__device__ __forceinline__ void ldsm4(const unsigned* base, int P, int r0, int kp,
                                      unsigned& o0, unsigned& o1, unsigned& o2, unsigned& o3) {
    int lane = threadIdx.x & 31;
    const unsigned* p = base + (r0 + (lane & 15)) * P + kp + ((lane >> 4) << 2);
    unsigned a = (unsigned)__cvta_generic_to_shared(p);
    asm volatile("ldmatrix.sync.aligned.m8n8.x4.shared.b16 {%0,%1,%2,%3}, [%4];"
                 : "=r"(o0), "=r"(o1), "=r"(o2), "=r"(o3) : "r"(a));
}

__device__ __forceinline__ void split2(float v0, float v1, unsigned& hi, unsigned& lo) {
    __nv_bfloat16 h0 = __float2bfloat16(v0);
    __nv_bfloat16 h1 = __float2bfloat16(v1);
    float r0 = v0 - __bfloat162float(h0);
    float r1 = v1 - __bfloat162float(h1);
    __nv_bfloat16 l0 = __float2bfloat16(r0);
    __nv_bfloat16 l1 = __float2bfloat16(r1);
    hi = (unsigned)__bfloat16_as_ushort(h0) | ((unsigned)__bfloat16_as_ushort(h1) << 16);
    lo = (unsigned)__bfloat16_as_ushort(l0) | ((unsigned)__bfloat16_as_ushort(l1) << 16);
}

__device__ __forceinline__ float2 unpack2(unsigned u) {
    __nv_bfloat162 b = *reinterpret_cast<__nv_bfloat162*>(&u);
    return __bfloat1622float2(b);
}

// ------------------------------ K0 ------------------------------------------
__global__ void k0_bias(const float* __restrict__ w1, const float* __restrict__ b1,
                        const float* __restrict__ w2) {
    __shared__ float tab[225][4];
    int tid = threadIdx.x;
    if (tid < 225) {
        int a = tid / 15, bb = tid % 15;
        float v0 = (a - 7) * (8.0f / 7.0f), v1 = (bb - 7) * (8.0f / 7.0f);
        float g0 = copysignf(log2f(fabsf(v0) + 1.0f) * (1.0f / 3.0f), v0);
        float g1 = copysignf(log2f(fabsf(v1) + 1.0f) * (1.0f / 3.0f), v1);
        float o0 = 0, o1 = 0, o2 = 0, o3 = 0;
        for (int j = 0; j < 512; j++) {
            float hv = fmaxf(w1[2 * j] * g0 + w1[2 * j + 1] * g1 + b1[j], 0.0f);
            o0 += hv * w2[j];        o1 += hv * w2[512 + j];
            o2 += hv * w2[1024 + j]; o3 += hv * w2[1536 + j];
        }
        tab[tid][0] = o0; tab[tid][1] = o1; tab[tid][2] = o2; tab[tid][3] = o3;
    }
    __syncthreads();
    for (int e = tid; e < 4 * 64 * 64; e += blockDim.x) {
        int h = e >> 12, i = (e >> 6) & 63, j = e & 63;
        int dy = (i >> 3) - (j >> 3) + 7, dx = (i & 7) - (j & 7) + 7;
        float v = tab[dy * 15 + dx][h];
        g_bias16[e] = 16.0f / (1.0f + expf(-v));
    }
}

__device__ __forceinline__ void splitpair(const float* w, unsigned* hi, unsigned* lo, int i) {
    split2(w[2 * i], w[2 * i + 1], hi[i], lo[i]);
}

__global__ void k0_wsplit(const float* __restrict__ qkvw, const float* __restrict__ pw,
                          const float* __restrict__ f1w, const float* __restrict__ f2w) {
    int i = blockIdx.x * 256 + threadIdx.x;
    if (i < 24576)       splitpair(qkvw, g_qkvh, g_qkvl, i);
    else if (i < 32768)  splitpair(pw,  g_pwh,  g_pwl,  i - 24576);
    else if (i < 65536)  splitpair(f1w, g_f1h,  g_f1l,  i - 32768);
    else if (i < 98304)  splitpair(f2w, g_f2h,  g_f2l,  i - 65536);
}

// ------------------------------ K1: attention -------------------------------
// word offsets
#define XHI   0        // [64][68] u32
#define XLO   4352     // ends 8704
#define QSPH  8704     // q splits [64][68] (all heads, dpair-packed)
#define QSPL  13056    // ends 17408
#define KSPH  17408
#define KSPL  21760    // ends 26112
#define PHI_  8704     // P splits [4][64][36] = 9216, over dead QSP
#define PLO_  17920    // ends 27136 (spills 1024 past KSP end)
#define WPH   8704     // proj wstage [64][68], over dead P
#define WPL   13056
#define VSPH  27136    // V splits [128][36] = 4608
#define VSPL  31744    // ends 36352
#define WQH   36352    // qkv wstage [64][68]
#define WQL   40704    // ends 45056
#define ATTN_ 36352    // [4][64][68] f32 = 17408, ends 53760 (over dead wstage)
#define OHI_  36352    // O splits [64][68], over dead ATTN after softmax
#define OLO_  40704    // ends 45056
#define POUT  45056    // [64][132] f32 = 8448, ends 53504
#define RG_   53760    // 64
#define IQ_   53824    // 256 (per head x token)
#define IK_   54080    // 256 -> 54336
#define K1_SMEM (54336 * 4)

__global__ void __launch_bounds__(512, 1)
k1_attn(const float* __restrict__ x,
        const float* __restrict__ n1w, const float* __restrict__ n1b,
        const float* __restrict__ qb, const float* __restrict__ vb,
        const float* __restrict__ ls, const float* __restrict__ pb) {
    extern __shared__ float sm[];
    unsigned* smu = (unsigned*)sm;
    int tid = threadIdx.x;
    int wid = tid >> 5, lane = tid & 31;
    int g = lane >> 2, q = lane & 3;
    int b = blockIdx.x >> 8, widx = blockIdx.x & 255;
    int wy = widx >> 4, wx = widx & 15;

    // phase 0: gather shifted window, split to bf16 pairs [t][cpair]
    {
        const float* xb = x + (size_t)b * 128 * HW;
#pragma unroll
        for (int it = 0; it < 8; it++) {              // 64 t * 64 cp
            int idx = it * 512 + tid;
            int t = idx & 63, cp = idx >> 6;
            int ti = t >> 3, tj = t & 7;
            int hh = (wy * 8 + ti + 4) & 127;
            int ww = (wx * 8 + tj + 4) & 127;
            const float* p = xb + (size_t)(2 * cp) * HW + hh * 128 + ww;
            float v0 = p[0], v1 = p[HW];
            split2(v0, v1, smu[XHI + t * 68 + cp], smu[XLO + t * 68 + cp]);
        }
        if (tid < 64) {
            int ti = tid >> 3, tj = tid & 7;
            int hs = wy * 8 + ti, ws = wx * 8 + tj;
            int hr = hs < 120 ? 0 : (hs < 124 ? 1 : 2);
            int wr = ws < 120 ? 0 : (ws < 124 ? 1 : 2);
            sm[RG_ + tid] = (float)(hr * 3 + wr);
        }
    }

    int mi = wid & 3, nhw = wid >> 2;   // 4 x 4 warp grid
    int m0 = mi * 16;
    int n0 = nhw * 16;

    // phase 1: QKV GEMM, 6 chunks of 64 cols; epilogue writes splits directly
    for (int ch = 0; ch < 6; ch++) {
        __syncthreads();
#pragma unroll
        for (int it = 0; it < 8; it++) {
            int p = it * 512 + tid;
            int r = p >> 6, c = p & 63;
            smu[WQH + r * 68 + c] = g_qkvh[(ch * 64 + r) * 64 + c];
            smu[WQL + r * 68 + c] = g_qkvl[(ch * 64 + r) * 64 + c];
        }
        __syncthreads();
        float acc[2][4] = {};
#pragma unroll
        for (int ks = 0; ks < 8; ks++) {
            int kp = ks * 8;
            unsigned ah0, ah1, ah2, ah3, al0, al1, al2, al3;
            ldsm4(smu + XHI, 68, m0, kp, ah0, ah1, ah2, ah3);
            ldsm4(smu + XLO, 68, m0, kp, al0, al1, al2, al3);
            unsigned bh0, bh1, bh2, bh3, bl0, bl1, bl2, bl3;
            ldsm4(smu + WQH, 68, n0, kp, bh0, bh1, bh2, bh3);
            ldsm4(smu + WQL, 68, n0, kp, bl0, bl1, bl2, bl3);
            mma_bf16(acc[0], ah0, ah1, ah2, ah3, bh0, bh2);
            mma_bf16(acc[0], ah0, ah1, ah2, ah3, bl0, bl2);
            mma_bf16(acc[0], al0, al1, al2, al3, bh0, bh2);
            mma_bf16(acc[1], ah0, ah1, ah2, ah3, bh1, bh3);
            mma_bf16(acc[1], ah0, ah1, ah2, ah3, bl1, bl3);
            mma_bf16(acc[1], al0, al1, al2, al3, bh1, bh3);
        }
        int r0 = m0 + g, r1 = r0 + 8;
        if (ch < 2) {          // Q cols 0..127 -> QSP [t][dpair]
#pragma unroll
            for (int nt = 0; nt < 2; nt++) {
                int col0 = ch * 64 + n0 + nt * 8 + 2 * q;
                float b0c = qb[col0], b1c = qb[col0 + 1];
                int dp = col0 >> 1;
                split2(acc[nt][0] + b0c, acc[nt][1] + b1c,
                       smu[QSPH + r0 * 68 + dp], smu[QSPL + r0 * 68 + dp]);
                split2(acc[nt][2] + b0c, acc[nt][3] + b1c,
                       smu[QSPH + r1 * 68 + dp], smu[QSPL + r1 * 68 + dp]);
            }
        } else if (ch < 4) {   // K cols 128..255 -> KSP
#pragma unroll
            for (int nt = 0; nt < 2; nt++) {
                int col0 = ch * 64 + n0 + nt * 8 + 2 * q;
                int dp = (col0 - 128) >> 1;
                split2(acc[nt][0], acc[nt][1],
                       smu[KSPH + r0 * 68 + dp], smu[KSPL + r0 * 68 + dp]);
                split2(acc[nt][2], acc[nt][3],
                       smu[KSPH + r1 * 68 + dp], smu[KSPL + r1 * 68 + dp]);
            }
        } else {               // V cols 256..383 -> VSP [d][upair] via lane exchange
#pragma unroll
            for (int nt = 0; nt < 2; nt++) {
                int col0 = ch * 64 + n0 + nt * 8 + 2 * q;
                int d0 = col0 - 256;
                float v0 = acc[nt][0] + vb[d0], v1 = acc[nt][1] + vb[d0 + 1];
                float v2 = acc[nt][2] + vb[d0], v3 = acc[nt][3] + vb[d0 + 1];
                float p0 = __shfl_xor_sync(0xffffffffu, v0, 4);
                float p1 = __shfl_xor_sync(0xffffffffu, v1, 4);
                float p2 = __shfl_xor_sync(0xffffffffu, v2, 4);
                float p3 = __shfl_xor_sync(0xffffffffu, v3, 4);
                if (!(g & 1)) {            // tokens (m0+g, m0+g+1)
                    int up = (m0 + g) >> 1;
                    split2(v0, p0, smu[VSPH + d0 * 36 + up], smu[VSPL + d0 * 36 + up]);
                    split2(v1, p1, smu[VSPH + (d0 + 1) * 36 + up], smu[VSPL + (d0 + 1) * 36 + up]);
                } else {                   // tokens (m0+g+7, m0+g+8)
                    int up = (m0 + g + 7) >> 1;
                    split2(p2, v2, smu[VSPH + d0 * 36 + up], smu[VSPL + d0 * 36 + up]);
                    split2(p3, v3, smu[VSPH + (d0 + 1) * 36 + up], smu[VSPL + (d0 + 1) * 36 + up]);
                }
            }
        }
    }
    __syncthreads();

    // phase 2: inverse norms, all heads, one pass (512 = 2 qk * 4 h * 64 t)
    {
        int qk = tid >> 8, rem = tid & 255;
        int h = rem >> 6, t = rem & 63;
        int base = (qk ? KSPH : QSPH) + t * 68 + h * 16;
        int baseL = base + (QSPL - QSPH);
        float s = 0.f;
#pragma unroll
        for (int i = 0; i < 16; i++) {
            float2 fh = unpack2(smu[base + i]);
            float2 fl = unpack2(smu[baseL + i]);
            float a0 = fh.x + fl.x, a1 = fh.y + fl.y;
            s += a0 * a0 + a1 * a1;
        }
        sm[(qk ? IK_ : IQ_) + h * 64 + t] = 1.0f / fmaxf(sqrtf(s), 1e-12f);
    }
    __syncthreads();

    // phase 3: logits MMA, all heads one pass. warp: head hw, m-tile mi.
    {
        int hw = wid >> 2;
        float scale = __expf(fminf(ls[hw], LOG100f));
        float acc[4][2][4];
#pragma unroll
        for (int i = 0; i < 4; i++)
#pragma unroll
            for (int j = 0; j < 2; j++)
#pragma unroll
                for (int k = 0; k < 4; k++) acc[i][j][k] = 0.f;
#pragma unroll
        for (int ks = 0; ks < 2; ks++) {
            int kp = hw * 16 + ks * 8;
            unsigned ah0, ah1, ah2, ah3, al0, al1, al2, al3;
            ldsm4(smu + QSPH, 68, m0, kp, ah0, ah1, ah2, ah3);
            ldsm4(smu + QSPL, 68, m0, kp, al0, al1, al2, al3);
#pragma unroll
            for (int nh = 0; nh < 4; nh++) {
                unsigned bh0, bh1, bh2, bh3, bl0, bl1, bl2, bl3;
                ldsm4(smu + KSPH, 68, nh * 16, kp, bh0, bh1, bh2, bh3);
                ldsm4(smu + KSPL, 68, nh * 16, kp, bl0, bl1, bl2, bl3);
                mma_bf16(acc[nh][0], ah0, ah1, ah2, ah3, bh0, bh2);
                mma_bf16(acc[nh][0], ah0, ah1, ah2, ah3, bl0, bl2);
                mma_bf16(acc[nh][0], al0, al1, al2, al3, bh0, bh2);
                mma_bf16(acc[nh][1], ah0, ah1, ah2, ah3, bh1, bh3);
                mma_bf16(acc[nh][1], ah0, ah1, ah2, ah3, bl1, bl3);
                mma_bf16(acc[nh][1], al0, al1, al2, al3, bh1, bh3);
            }
        }
        int r0 = m0 + g, r1 = r0 + 8;
        float iq0 = sm[IQ_ + hw * 64 + r0] * scale;
        float iq1 = sm[IQ_ + hw * 64 + r1] * scale;
        float rt0 = sm[RG_ + r0], rt1 = sm[RG_ + r1];
        float* A = &sm[ATTN_ + hw * 4352];
#pragma unroll
        for (int nh = 0; nh < 4; nh++)
#pragma unroll
            for (int nt = 0; nt < 2; nt++) {
                int col = nh * 16 + nt * 8 + 2 * q;
                float ik0 = sm[IK_ + hw * 64 + col], ik1 = sm[IK_ + hw * 64 + col + 1];
                float ru0 = sm[RG_ + col], ru1 = sm[RG_ + col + 1];
                float2 b0v = *(const float2*)&g_bias16[(hw * 64 + r0) * 64 + col];
                float2 b1v = *(const float2*)&g_bias16[(hw * 64 + r1) * 64 + col];
                A[r0 * 68 + col]     = acc[nh][nt][0] * iq0 * ik0 + b0v.x + (rt0 != ru0 ? -100.f : 0.f);
                A[r0 * 68 + col + 1] = acc[nh][nt][1] * iq0 * ik1 + b0v.y + (rt0 != ru1 ? -100.f : 0.f);
                A[r1 * 68 + col]     = acc[nh][nt][2] * iq1 * ik0 + b1v.x + (rt1 != ru0 ? -100.f : 0.f);
                A[r1 * 68 + col + 1] = acc[nh][nt][3] * iq1 * ik1 + b1v.y + (rt1 != ru1 ? -100.f : 0.f);
            }
    }
    __syncthreads();

    // phase 4: softmax, all 256 rows (2 threads/row) -> P splits [h][t][upair]
    {
        int r = tid >> 1, half = tid & 1;
        int hw = r >> 6, t = r & 63;
        const float* row = &sm[ATTN_ + hw * 4352 + t * 68 + half * 32];
        float e[32];
        float mx = -1e30f;
#pragma unroll
        for (int i = 0; i < 32; i++) { e[i] = row[i]; mx = fmaxf(mx, e[i]); }
        mx = fmaxf(mx, __shfl_xor_sync(0xffffffffu, mx, 1));
        float s = 0.f;
#pragma unroll
        for (int i = 0; i < 32; i++) { e[i] = __expf(e[i] - mx); s += e[i]; }
        s += __shfl_xor_sync(0xffffffffu, s, 1);
        float inv = 1.0f / s;
        int pb_ = hw * 2304 + t * 36 + half * 16;
#pragma unroll
        for (int i = 0; i < 16; i++)
            split2(e[2 * i] * inv, e[2 * i + 1] * inv,
                   smu[PHI_ + pb_ + i], smu[PLO_ + pb_ + i]);
    }
    __syncthreads();

    // phase 5: PV MMA, all heads one pass. warp: head hw, m-tile mi, 2 n-tiles
    {
        int hw = wid >> 2;
        const unsigned* PH = smu + PHI_ + hw * 2304;
        const unsigned* PL = smu + PLO_ + hw * 2304;
        float acc[2][2][4];
#pragma unroll
        for (int i = 0; i < 2; i++)
#pragma unroll
            for (int j = 0; j < 2; j++)
#pragma unroll
                for (int k = 0; k < 4; k++) acc[i][j][k] = 0.f;
#pragma unroll
        for (int ks = 0; ks < 4; ks++) {
            int kp = ks * 8;
            unsigned ah0, ah1, ah2, ah3, al0, al1, al2, al3;
            ldsm4(PH, 36, m0, kp, ah0, ah1, ah2, ah3);
            ldsm4(PL, 36, m0, kp, al0, al1, al2, al3);
#pragma unroll
            for (int nd = 0; nd < 2; nd++) {
                int n0v = hw * 32 + nd * 16;
                unsigned bh0, bh1, bh2, bh3, bl0, bl1, bl2, bl3;
                ldsm4(smu + VSPH, 36, n0v, kp, bh0, bh1, bh2, bh3);
                ldsm4(smu + VSPL, 36, n0v, kp, bl0, bl1, bl2, bl3);
                mma_bf16(acc[nd][0], ah0, ah1, ah2, ah3, bh0, bh2);
                mma_bf16(acc[nd][0], ah0, ah1, ah2, ah3, bl0, bl2);
                mma_bf16(acc[nd][0], al0, al1, al2, al3, bh0, bh2);
                mma_bf16(acc[nd][1], ah0, ah1, ah2, ah3, bh1, bh3);
                mma_bf16(acc[nd][1], ah0, ah1, ah2, ah3, bl1, bl3);
                mma_bf16(acc[nd][1], al0, al1, al2, al3, bh1, bh3);
            }
        }
        int r0 = m0 + g, r1 = r0 + 8;
#pragma unroll
        for (int nd = 0; nd < 2; nd++)
#pragma unroll
            for (int nt = 0; nt < 2; nt++) {
                int dglob = hw * 32 + nd * 16 + nt * 8 + 2 * q;
                int dp = dglob >> 1;
                split2(acc[nd][nt][0], acc[nd][nt][1],
                       smu[OHI_ + r0 * 68 + dp], smu[OLO_ + r0 * 68 + dp]);
                split2(acc[nd][nt][2], acc[nd][nt][3],
                       smu[OHI_ + r1 * 68 + dp], smu[OLO_ + r1 * 68 + dp]);
            }
    }

    // phase 6: proj GEMM, 2 chunks of 64 cols -> Pout f32 rows [t][132]
    for (int ch = 0; ch < 2; ch++) {
        __syncthreads();
#pragma unroll
        for (int it = 0; it < 8; it++) {
            int p = it * 512 + tid;
            int r = p >> 6, c = p & 63;
            smu[WPH + r * 68 + c] = g_pwh[(ch * 64 + r) * 64 + c];
            smu[WPL + r * 68 + c] = g_pwl[(ch * 64 + r) * 64 + c];
        }
        __syncthreads();
        float acc[2][4] = {};
#pragma unroll
        for (int ks = 0; ks < 8; ks++) {
            int kp = ks * 8;
            unsigned ah0, ah1, ah2, ah3, al0, al1, al2, al3;
            ldsm4(smu + OHI_, 68, m0, kp, ah0, ah1, ah2, ah3);
            ldsm4(smu + OLO_, 68, m0, kp, al0, al1, al2, al3);
            unsigned bh0, bh1, bh2, bh3, bl0, bl1, bl2, bl3;
            ldsm4(smu + WPH, 68, n0, kp, bh0, bh1, bh2, bh3);
            ldsm4(smu + WPL, 68, n0, kp, bl0, bl1, bl2, bl3);
            mma_bf16(acc[0], ah0, ah1, ah2, ah3, bh0, bh2);
            mma_bf16(acc[0], ah0, ah1, ah2, ah3, bl0, bl2);
            mma_bf16(acc[0], al0, al1, al2, al3, bh0, bh2);
            mma_bf16(acc[1], ah0, ah1, ah2, ah3, bh1, bh3);
            mma_bf16(acc[1], ah0, ah1, ah2, ah3, bl1, bl3);
            mma_bf16(acc[1], al0, al1, al2, al3, bh1, bh3);
        }
        int r0 = m0 + g, r1 = r0 + 8;
#pragma unroll
        for (int nt = 0; nt < 2; nt++) {
            int col0 = ch * 64 + n0 + nt * 8 + 2 * q;
            sm[POUT + r0 * 132 + col0]     = acc[nt][0] + pb[col0];
            sm[POUT + r0 * 132 + col0 + 1] = acc[nt][1] + pb[col0 + 1];
            sm[POUT + r1 * 132 + col0]     = acc[nt][2] + pb[col0];
            sm[POUT + r1 * 132 + col0 + 1] = acc[nt][3] + pb[col0 + 1];
        }
    }
    __syncthreads();

    // phase 7: LN + residual -> g_x1 (8 threads/row)
    {
        int t = tid >> 3, ln = tid & 7;
        const float* prow = &sm[POUT + t * 132];
        int cb = ln * 16;
        float s1 = 0.f, s2 = 0.f;
#pragma unroll
        for (int c = 0; c < 16; c++) {
            float v = prow[cb + c];
            s1 += v; s2 += v * v;
        }
        s1 += __shfl_xor_sync(0xffffffffu, s1, 1);
        s2 += __shfl_xor_sync(0xffffffffu, s2, 1);
        s1 += __shfl_xor_sync(0xffffffffu, s1, 2);
        s2 += __shfl_xor_sync(0xffffffffu, s2, 2);
        s1 += __shfl_xor_sync(0xffffffffu, s1, 4);
        s2 += __shfl_xor_sync(0xffffffffu, s2, 4);
        float mu = s1 * (1.0f / 128.0f);
        float var = fmaxf(s2 * (1.0f / 128.0f) - mu * mu, 0.0f);
        float rs = rsqrtf(var + 1e-5f);
        int ti = t >> 3, tj = t & 7;
        int hh = (wy * 8 + ti + 4) & 127;
        int ww = (wx * 8 + tj + 4) & 127;
        float* dst = &g_x1[((size_t)b * HW + hh * 128 + ww) * 128];
#pragma unroll
        for (int cp = 0; cp < 8; cp++) {
            unsigned uh = smu[XHI + t * 68 + ln * 8 + cp];
            unsigned ul = smu[XLO + t * 68 + ln * 8 + cp];
            float2 fh = unpack2(uh), fl = unpack2(ul);
            int cc = cb + 2 * cp;
            float l0 = (prow[cc] - mu) * rs * n1w[cc] + n1b[cc];
            float l1 = (prow[cc + 1] - mu) * rs * n1w[cc + 1] + n1b[cc + 1];
            dst[cc]     = fh.x + fl.x + l0;
            dst[cc + 1] = fh.y + fl.y + l1;
        }
    }
}

// ------------------------------ K2: MLP (128 tokens/CTA) — unchanged R8 -----
#define K2XHI 0
#define K2XLO 8704
#define K2W1H 17408
#define K2W1L 21760
#define K2HH  26112
#define K2HL  30720
#define K2W2H 35328
#define K2W2L 39936
#define K2Y   26112
#define K2_SMEM (44544 * 4)

__global__ void __launch_bounds__(512, 1)
k2_mlp(const float* __restrict__ n2w, const float* __restrict__ n2b,
       const float* __restrict__ b1, const float* __restrict__ b2,
       float* __restrict__ out) {
    extern __shared__ float sm[];
    unsigned* smu = (unsigned*)sm;
    int tid = threadIdx.x;
    int wid = tid >> 5, lane = tid & 31;
    int g = lane >> 2, q = lane & 3;
    int p0 = blockIdx.x * 128;
    int b = p0 >> 14, h = (p0 >> 7) & 127;

#pragma unroll
    for (int it = 0; it < 16; it++) {
        int idx = it * 512 + tid;
        int cp = idx & 63, t = idx >> 6;
        float2 v = *(const float2*)&g_x1[((size_t)p0 + t) * 128 + 2 * cp];
        split2(v.x, v.y, smu[K2XHI + t * 68 + cp], smu[K2XLO + t * 68 + cp]);
    }

    int mi = wid & 7, nh = wid >> 3;
    int m0 = mi * 16;
    int n0w = nh * 32;
    float acc2[8][4];
#pragma unroll
    for (int t = 0; t < 8; t++)
#pragma unroll
        for (int j = 0; j < 4; j++) acc2[t][j] = 0.f;

    for (int ch = 0; ch < 8; ch++) {
        __syncthreads();
#pragma unroll
        for (int it = 0; it < 8; it++) {
            int p = it * 512 + tid;
            int r = p >> 6, c = p & 63;
            smu[K2W1H + r * 68 + c] = g_f1h[(ch * 64 + r) * 64 + c];
            smu[K2W1L + r * 68 + c] = g_f1l[(ch * 64 + r) * 64 + c];
        }
#pragma unroll
        for (int it = 0; it < 8; it++) {
            int p = it * 512 + tid;
            int r = p >> 5, c = p & 31;
            smu[K2W2H + r * 36 + c] = g_f2h[r * 256 + ch * 32 + c];
            smu[K2W2L + r * 36 + c] = g_f2l[r * 256 + ch * 32 + c];
        }
        __syncthreads();
        float acc[4][4] = {};
#pragma unroll
        for (int ks = 0; ks < 8; ks++) {
            int kp = ks * 8;
            unsigned ah0, ah1, ah2, ah3, al0, al1, al2, al3;
            ldsm4(smu + K2XHI, 68, m0, kp, ah0, ah1, ah2, ah3);
            ldsm4(smu + K2XLO, 68, m0, kp, al0, al1, al2, al3);
#pragma unroll
            for (int hf = 0; hf < 2; hf++) {
                unsigned bh0, bh1, bh2, bh3, bl0, bl1, bl2, bl3;
                ldsm4(smu + K2W1H, 68, n0w + 16 * hf, kp, bh0, bh1, bh2, bh3);
                ldsm4(smu + K2W1L, 68, n0w + 16 * hf, kp, bl0, bl1, bl2, bl3);
                mma_bf16(acc[2 * hf],     ah0, ah1, ah2, ah3, bh0, bh2);
                mma_bf16(acc[2 * hf],     ah0, ah1, ah2, ah3, bl0, bl2);
                mma_bf16(acc[2 * hf],     al0, al1, al2, al3, bh0, bh2);
                mma_bf16(acc[2 * hf + 1], ah0, ah1, ah2, ah3, bh1, bh3);
                mma_bf16(acc[2 * hf + 1], ah0, ah1, ah2, ah3, bl1, bl3);
                mma_bf16(acc[2 * hf + 1], al0, al1, al2, al3, bh1, bh3);
            }
        }
#pragma unroll
        for (int nt = 0; nt < 4; nt++) {
            int c0 = n0w + nt * 8 + 2 * q;
            int col = ch * 64 + c0;
            float v0 = acc[nt][0] + b1[col],     v1 = acc[nt][1] + b1[col + 1];
            float v2 = acc[nt][2] + b1[col],     v3 = acc[nt][3] + b1[col + 1];
            v0 = v0 / (1.0f + __expf(-v0));
            v1 = v1 / (1.0f + __expf(-v1));
            v2 = v2 / (1.0f + __expf(-v2));
            v3 = v3 / (1.0f + __expf(-v3));
            int pp = (c0 >> 1);
            split2(v0, v1, smu[K2HH + (m0 + g) * 36 + pp], smu[K2HL + (m0 + g) * 36 + pp]);
            split2(v2, v3, smu[K2HH + (m0 + g + 8) * 36 + pp], smu[K2HL + (m0 + g + 8) * 36 + pp]);
        }
        __syncthreads();
#pragma unroll
        for (int ks = 0; ks < 4; ks++) {
            int kp = ks * 8;
            unsigned ah0, ah1, ah2, ah3, al0, al1, al2, al3;
            ldsm4(smu + K2HH, 36, m0, kp, ah0, ah1, ah2, ah3);
            ldsm4(smu + K2HL, 36, m0, kp, al0, al1, al2, al3);
#pragma unroll
            for (int tp = 0; tp < 4; tp++) {
                unsigned bh0, bh1, bh2, bh3, bl0, bl1, bl2, bl3;
                ldsm4(smu + K2W2H, 36, nh * 64 + 16 * tp, kp, bh0, bh1, bh2, bh3);
                ldsm4(smu + K2W2L, 36, nh * 64 + 16 * tp, kp, bl0, bl1, bl2, bl3);
                mma_bf16(acc2[2 * tp],     ah0, ah1, ah2, ah3, bh0, bh2);
                mma_bf16(acc2[2 * tp],     ah0, ah1, ah2, ah3, bl0, bl2);
                mma_bf16(acc2[2 * tp],     al0, al1, al2, al3, bh0, bh2);
                mma_bf16(acc2[2 * tp + 1], ah0, ah1, ah2, ah3, bh1, bh3);
                mma_bf16(acc2[2 * tp + 1], ah0, ah1, ah2, ah3, bl1, bl3);
                mma_bf16(acc2[2 * tp + 1], al0, al1, al2, al3, bh1, bh3);
            }
        }
    }
    __syncthreads();
#pragma unroll
    for (int t = 0; t < 8; t++) {
        int col = nh * 64 + t * 8 + 2 * q;
        sm[K2Y + (m0 + g) * 133 + col]         = acc2[t][0] + b2[col];
        sm[K2Y + (m0 + g) * 133 + col + 1]     = acc2[t][1] + b2[col + 1];
        sm[K2Y + (m0 + g + 8) * 133 + col]     = acc2[t][2] + b2[col];
        sm[K2Y + (m0 + g + 8) * 133 + col + 1] = acc2[t][3] + b2[col + 1];
    }
    __syncthreads();
    {
        int t = tid >> 2, ln = tid & 3;
        float* yrow = &sm[K2Y + t * 133];
        int cb = ln * 32;
        float s1 = 0.f, s2 = 0.f;
#pragma unroll 8
        for (int c = 0; c < 32; c++) {
            float v = yrow[cb + c];
            s1 += v; s2 += v * v;
        }
        s1 += __shfl_xor_sync(0xffffffffu, s1, 1);
        s2 += __shfl_xor_sync(0xffffffffu, s2, 1);
        s1 += __shfl_xor_sync(0xffffffffu, s1, 2);
        s2 += __shfl_xor_sync(0xffffffffu, s2, 2);
        float mu = s1 * (1.0f / 128.0f);
        float var = fmaxf(s2 * (1.0f / 128.0f) - mu * mu, 0.0f);
        float rs = rsqrtf(var + 1e-5f);
#pragma unroll 8
        for (int cp = 0; cp < 16; cp++) {
            unsigned uh = smu[K2XHI + t * 68 + (cb >> 1) + cp];
            unsigned ul = smu[K2XLO + t * 68 + (cb >> 1) + cp];
            float2 fh = unpack2(uh), fl = unpack2(ul);
            int cc = cb + 2 * cp;
            float l0 = (yrow[cc] - mu) * rs * n2w[cc] + n2b[cc];
            float l1 = (yrow[cc + 1] - mu) * rs * n2w[cc + 1] + n2b[cc + 1];
            yrow[cc]     = fh.x + fl.x + l0;
            yrow[cc + 1] = fh.y + fl.y + l1;
        }
    }
    __syncthreads();
    {
        float* ob = out + (size_t)b * 128 * HW + h * 128;
#pragma unroll
        for (int it = 0; it < 32; it++) {
            int idx = it * 512 + tid;
            int c = idx >> 7, w = idx & 127;
            ob[(size_t)c * HW + w] = sm[K2Y + w * 133 + c];
        }
    }
}

// ------------------------------ launch --------------------------------------
extern "C" void kernel_launch(void* const* d_in, const int* in_sizes, int n_in,
                              void* d_out, int out_size) {
    const float* x    = (const float*)d_in[0];
    const float* n1w  = (const float*)d_in[1];
    const float* n1b  = (const float*)d_in[2];
    const float* qkvw = (const float*)d_in[3];
    const float* qb   = (const float*)d_in[4];
    const float* vb   = (const float*)d_in[5];
    const float* ls   = (const float*)d_in[6];
    const float* cw1  = (const float*)d_in[7];
    const float* cb1  = (const float*)d_in[8];
    const float* cw2  = (const float*)d_in[9];
    const float* pw   = (const float*)d_in[10];
    const float* pb   = (const float*)d_in[11];
    const float* n2w  = (const float*)d_in[12];
    const float* n2b  = (const float*)d_in[13];
    const float* f1w  = (const float*)d_in[14];
    const float* f1b  = (const float*)d_in[15];
    const float* f2w  = (const float*)d_in[16];
    const float* f2b  = (const float*)d_in[17];
    float* out = (float*)d_out;

    cudaFuncSetAttribute(k1_attn, cudaFuncAttributeMaxDynamicSharedMemorySize, K1_SMEM);
    cudaFuncSetAttribute(k2_mlp,  cudaFuncAttributeMaxDynamicSharedMemorySize, K2_SMEM);

    k0_bias<<<1, 256>>>(cw1, cb1, cw2);
    k0_wsplit<<<384, 256>>>(qkvw, pw, f1w, f2w);
    k1_attn<<<4096, 512, K1_SMEM>>>(x, n1w, n1b, qb, vb, ls, pb);
    k2_mlp<<<2048, 512, K2_SMEM>>>(n2w, n2b, f1b, f2b, out);
}